// round 1
// baseline (speedup 1.0000x reference)
#include <cuda_runtime.h>
#include <math.h>

#define Lq 4096
#define Dq 1024
#define Hq 16
#define HDq 64
#define Mq 4096

// ---------------- scratch (device globals; no allocation allowed) ----------
__device__ float g_xln [Lq*Dq];            // 16 MB  LN0 output
__device__ float g_qkv [Lq*3*Dq];          // 48 MB  qkv (rope applied in place)
__device__ float g_attn[Lq*Dq];            // 16 MB  attention output (l, h*64+d)
__device__ float g_h   [Lq*Dq];            // 16 MB  residual + attn@w_o
__device__ float g_yln [Lq*Dq];            // 16 MB  LN1 output
__device__ float g_fc0 [(size_t)Lq*Mq];    // 64 MB  gelu(fc0)

// ---------------- LayerNorm: one block per row, 256 threads ----------------
__global__ void __launch_bounds__(256) ln_kernel(const float* __restrict__ x,
                                                 const float* __restrict__ g,
                                                 const float* __restrict__ b,
                                                 float* __restrict__ out) {
    int row = blockIdx.x;
    int tid = threadIdx.x;
    const float* xr = x + (size_t)row * Dq;
    float4 v = *(const float4*)&xr[tid * 4];
    float sum = v.x + v.y + v.z + v.w;
    float sq  = v.x*v.x + v.y*v.y + v.z*v.z + v.w*v.w;
    // warp reduce
    #pragma unroll
    for (int o = 16; o; o >>= 1) {
        sum += __shfl_xor_sync(0xffffffffu, sum, o);
        sq  += __shfl_xor_sync(0xffffffffu, sq,  o);
    }
    __shared__ float red0[8], red1[8];
    int wid = tid >> 5, lane = tid & 31;
    if (lane == 0) { red0[wid] = sum; red1[wid] = sq; }
    __syncthreads();
    float tot = 0.f, totq = 0.f;
    #pragma unroll
    for (int i = 0; i < 8; i++) { tot += red0[i]; totq += red1[i]; }
    float mu  = tot * (1.0f / Dq);
    float var = totq * (1.0f / Dq) - mu * mu;
    float inv = rsqrtf(var + 1e-5f);
    float4 gv = *(const float4*)&g[tid * 4];
    float4 bv = *(const float4*)&b[tid * 4];
    float4 o4;
    o4.x = (v.x - mu) * inv * gv.x + bv.x;
    o4.y = (v.y - mu) * inv * gv.y + bv.y;
    o4.z = (v.z - mu) * inv * gv.z + bv.z;
    o4.w = (v.w - mu) * inv * gv.w + bv.w;
    *(float4*)&out[(size_t)row * Dq + tid * 4] = o4;
}

// ---------------- RoPE in place on q and k parts of g_qkv -------------------
__global__ void __launch_bounds__(256) rope_kernel(const float* __restrict__ freqs) {
    int idx = blockIdx.x * blockDim.x + threadIdx.x;   // over L*H*32
    if (idx >= Lq * Hq * (HDq / 2)) return;
    int t = idx & 31;
    int h = (idx >> 5) & 15;
    int l = idx >> 9;
    float c = freqs[((size_t)l * 32 + t) * 2 + 0];
    float s = freqs[((size_t)l * 32 + t) * 2 + 1];
    #pragma unroll
    for (int part = 0; part < 2; part++) {
        float* p = &g_qkv[(size_t)l * (3 * Dq) + part * Dq + h * HDq + 2 * t];
        float a = p[0], bb = p[1];
        p[0] = a * c - bb * s;
        p[1] = a * s + bb * c;
    }
}

// ---------------- GELU (exact) ----------------------------------------------
__device__ __forceinline__ float gelu_exact(float x) {
    return 0.5f * x * (1.0f + erff(x * 0.70710678118654752f));
}

// ---------------- SGEMM 128x128x8, 256 threads, 8x8 microtile ---------------
// EPI: 0 = none, 1 = +bias then gelu, 2 = +res, 3 = +bias +res
template <int EPI>
__global__ void __launch_bounds__(256) sgemm(const float* __restrict__ A,
                                             const float* __restrict__ B,
                                             const float* __restrict__ bias,
                                             const float* __restrict__ res,
                                             float* __restrict__ C,
                                             int N, int K) {
    __shared__ float As[8][128];
    __shared__ float Bs[8][128];
    int tid = threadIdx.x;
    int bx = blockIdx.x, by = blockIdx.y;
    int tx = tid & 15, ty = tid >> 4;

    int arow  = tid >> 1;           // 0..127
    int acol4 = (tid & 1) * 4;      // 0 or 4
    int brow  = tid >> 5;           // 0..7
    int bcol4 = (tid & 31) * 4;     // 0..124

    const float* Aptr = A + (size_t)(by * 128 + arow) * K + acol4;
    const float* Bptr = B + (size_t)brow * N + bx * 128 + bcol4;

    float acc[8][8];
    #pragma unroll
    for (int i = 0; i < 8; i++)
        #pragma unroll
        for (int j = 0; j < 8; j++) acc[i][j] = 0.f;

    for (int k0 = 0; k0 < K; k0 += 8) {
        float4 av = *(const float4*)(Aptr + k0);
        float4 bv = *(const float4*)(Bptr + (size_t)k0 * N);
        As[acol4 + 0][arow] = av.x;
        As[acol4 + 1][arow] = av.y;
        As[acol4 + 2][arow] = av.z;
        As[acol4 + 3][arow] = av.w;
        *(float4*)&Bs[brow][bcol4] = bv;
        __syncthreads();
        #pragma unroll
        for (int k = 0; k < 8; k++) {
            float a[8], b[8];
            *(float4*)&a[0] = *(const float4*)&As[k][ty * 8];
            *(float4*)&a[4] = *(const float4*)&As[k][ty * 8 + 4];
            *(float4*)&b[0] = *(const float4*)&Bs[k][tx * 8];
            *(float4*)&b[4] = *(const float4*)&Bs[k][tx * 8 + 4];
            #pragma unroll
            for (int i = 0; i < 8; i++)
                #pragma unroll
                for (int j = 0; j < 8; j++)
                    acc[i][j] += a[i] * b[j];
        }
        __syncthreads();
    }

    int col0 = bx * 128 + tx * 8;
    #pragma unroll
    for (int i = 0; i < 8; i++) {
        int row = by * 128 + ty * 8 + i;
        size_t base = (size_t)row * N + col0;
        #pragma unroll
        for (int j = 0; j < 8; j += 4) {
            float r0 = acc[i][j + 0], r1 = acc[i][j + 1];
            float r2 = acc[i][j + 2], r3 = acc[i][j + 3];
            if (EPI == 1 || EPI == 3) {
                r0 += bias[col0 + j + 0];
                r1 += bias[col0 + j + 1];
                r2 += bias[col0 + j + 2];
                r3 += bias[col0 + j + 3];
            }
            if (EPI == 1) {
                r0 = gelu_exact(r0); r1 = gelu_exact(r1);
                r2 = gelu_exact(r2); r3 = gelu_exact(r3);
            }
            if (EPI == 2 || EPI == 3) {
                float4 rv = *(const float4*)&res[base + j];
                r0 += rv.x; r1 += rv.y; r2 += rv.z; r3 += rv.w;
            }
            float4 o4 = make_float4(r0, r1, r2, r3);
            *(float4*)&C[base + j] = o4;
        }
    }
}

// ---------------- Attention: flash-style, 1 q-row per thread ----------------
// grid = (16 qtiles, 16 heads, 4 segments), 64 threads per block.
__global__ void __launch_bounds__(64) attn_kernel() {
    int qt   = blockIdx.x;
    int head = blockIdx.y;
    int seg  = blockIdx.z;
    int tid  = threadIdx.x;
    int qrow = seg * 1024 + qt * 64 + tid;

    __shared__ float Ks[64][64];
    __shared__ float Vs[64][64];

    const float scale = 0.125f;  // 1/sqrt(64)
    float q[64];
    {
        const float* qp = &g_qkv[(size_t)qrow * (3 * Dq) + head * HDq];
        #pragma unroll
        for (int d = 0; d < 64; d += 4) {
            float4 v = *(const float4*)&qp[d];
            q[d] = v.x * scale; q[d + 1] = v.y * scale;
            q[d + 2] = v.z * scale; q[d + 3] = v.w * scale;
        }
    }

    float o[64];
    #pragma unroll
    for (int d = 0; d < 64; d++) o[d] = 0.f;
    float m = -1e30f, lsum = 0.f;

    for (int kc = 0; kc < 16; kc++) {
        __syncthreads();
        // load 64 K rows + 64 V rows for this head/segment chunk
        for (int idx = tid; idx < 64 * 64; idx += 64) {
            int r = idx >> 6, d = idx & 63;
            size_t base = (size_t)(seg * 1024 + kc * 64 + r) * (3 * Dq) + head * HDq + d;
            Ks[r][d] = g_qkv[base + Dq];
            Vs[r][d] = g_qkv[base + 2 * Dq];
        }
        __syncthreads();

        float s[64];
        float mc = -1e30f;
        #pragma unroll
        for (int j = 0; j < 64; j++) {
            float a = 0.f;
            #pragma unroll
            for (int d = 0; d < 64; d += 4) {
                float4 kv = *(const float4*)&Ks[j][d];
                a += q[d] * kv.x + q[d + 1] * kv.y + q[d + 2] * kv.z + q[d + 3] * kv.w;
            }
            s[j] = a;
            mc = fmaxf(mc, a);
        }
        float mnew = fmaxf(m, mc);
        float corr = __expf(m - mnew);
        m = mnew;
        lsum *= corr;
        #pragma unroll
        for (int d = 0; d < 64; d++) o[d] *= corr;
        #pragma unroll
        for (int j = 0; j < 64; j++) {
            float p = __expf(s[j] - mnew);
            lsum += p;
            #pragma unroll
            for (int d = 0; d < 64; d += 4) {
                float4 vv = *(const float4*)&Vs[j][d];
                o[d]     += p * vv.x;
                o[d + 1] += p * vv.y;
                o[d + 2] += p * vv.z;
                o[d + 3] += p * vv.w;
            }
        }
    }

    float inv = 1.0f / lsum;
    float* op = &g_attn[(size_t)qrow * Dq + head * HDq];
    #pragma unroll
    for (int d = 0; d < 64; d += 4) {
        float4 o4 = make_float4(o[d] * inv, o[d + 1] * inv, o[d + 2] * inv, o[d + 3] * inv);
        *(float4*)&op[d] = o4;
    }
}

// ---------------- host orchestration ---------------------------------------
extern "C" void kernel_launch(void* const* d_in, const int* in_sizes, int n_in,
                              void* d_out, int out_size) {
    const float* hidden = (const float*)d_in[0];
    // d_in[1] = cu_seqlens (fixed [0,1024,2048,3072,4096]); segments hardcoded
    const float* rope   = (const float*)d_in[2];
    const float* ln0_g  = (const float*)d_in[3];
    const float* ln0_b  = (const float*)d_in[4];
    const float* ln1_g  = (const float*)d_in[5];
    const float* ln1_b  = (const float*)d_in[6];
    const float* w_qkv  = (const float*)d_in[7];
    const float* w_o    = (const float*)d_in[8];
    const float* w_fc0  = (const float*)d_in[9];
    const float* b_fc0  = (const float*)d_in[10];
    const float* w_fc1  = (const float*)d_in[11];
    const float* b_fc1  = (const float*)d_in[12];
    float* out = (float*)d_out;

    float *p_xln, *p_qkv, *p_attn, *p_h, *p_yln, *p_fc0;
    cudaGetSymbolAddress((void**)&p_xln,  g_xln);
    cudaGetSymbolAddress((void**)&p_qkv,  g_qkv);
    cudaGetSymbolAddress((void**)&p_attn, g_attn);
    cudaGetSymbolAddress((void**)&p_h,    g_h);
    cudaGetSymbolAddress((void**)&p_yln,  g_yln);
    cudaGetSymbolAddress((void**)&p_fc0,  g_fc0);

    // 1. LN0
    ln_kernel<<<Lq, 256>>>(hidden, ln0_g, ln0_b, p_xln);

    // 2. QKV = xln @ w_qkv   [4096 x 3072], K=1024
    sgemm<0><<<dim3(3 * Dq / 128, Lq / 128), 256>>>(p_xln, w_qkv, nullptr, nullptr,
                                                    p_qkv, 3 * Dq, Dq);
    // 3. RoPE in place on q,k
    rope_kernel<<<(Lq * Hq * 32) / 256, 256>>>(rope);

    // 4. Attention (block-diagonal, 4 segments of 1024)
    attn_kernel<<<dim3(16, Hq, 4), 64>>>();

    // 5. h = hidden + attn @ w_o   [4096 x 1024], K=1024
    sgemm<2><<<dim3(Dq / 128, Lq / 128), 256>>>(p_attn, w_o, nullptr, hidden,
                                                p_h, Dq, Dq);
    // 6. LN1
    ln_kernel<<<Lq, 256>>>(p_h, ln1_g, ln1_b, p_yln);

    // 7. fc0 + bias + gelu   [4096 x 4096], K=1024
    sgemm<1><<<dim3(Mq / 128, Lq / 128), 256>>>(p_yln, w_fc0, b_fc0, nullptr,
                                                p_fc0, Mq, Dq);
    // 8. out = h + fc0g @ w_fc1 + b_fc1   [4096 x 1024], K=4096
    sgemm<3><<<dim3(Dq / 128, Lq / 128), 256>>>(p_fc0, w_fc1, b_fc1, p_h,
                                                out, Dq, Mq);
    (void)in_sizes; (void)n_in; (void)out_size;
}

// round 2
// speedup vs baseline: 1.7436x; 1.7436x over previous
#include <cuda_runtime.h>
#include <math.h>
#include <stdint.h>

#define Lq 4096
#define Dq 1024
#define Hq 16
#define HDq 64
#define Mq 4096

// ---------------- scratch (device globals; no allocation allowed) ----------
__device__ float g_xln [Lq*Dq];            // 16 MB  LN0 output
__device__ float g_qkv [Lq*3*Dq];          // 48 MB  qkv (rope applied in place)
__device__ float g_attn[Lq*Dq];            // 16 MB  attention output (l, h*64+d)
__device__ float g_h   [Lq*Dq];            // 16 MB  residual + attn@w_o
__device__ float g_yln [Lq*Dq];            // 16 MB  LN1 output
__device__ float g_fc0 [(size_t)Lq*Mq];    // 64 MB  gelu(fc0)

// ---------------- LayerNorm: one block per row, 256 threads ----------------
__global__ void __launch_bounds__(256) ln_kernel(const float* __restrict__ x,
                                                 const float* __restrict__ g,
                                                 const float* __restrict__ b,
                                                 float* __restrict__ out) {
    int row = blockIdx.x;
    int tid = threadIdx.x;
    const float* xr = x + (size_t)row * Dq;
    float4 v = *(const float4*)&xr[tid * 4];
    float sum = v.x + v.y + v.z + v.w;
    float sq  = v.x*v.x + v.y*v.y + v.z*v.z + v.w*v.w;
    #pragma unroll
    for (int o = 16; o; o >>= 1) {
        sum += __shfl_xor_sync(0xffffffffu, sum, o);
        sq  += __shfl_xor_sync(0xffffffffu, sq,  o);
    }
    __shared__ float red0[8], red1[8];
    int wid = tid >> 5, lane = tid & 31;
    if (lane == 0) { red0[wid] = sum; red1[wid] = sq; }
    __syncthreads();
    float tot = 0.f, totq = 0.f;
    #pragma unroll
    for (int i = 0; i < 8; i++) { tot += red0[i]; totq += red1[i]; }
    float mu  = tot * (1.0f / Dq);
    float var = totq * (1.0f / Dq) - mu * mu;
    float inv = rsqrtf(var + 1e-5f);
    float4 gv = *(const float4*)&g[tid * 4];
    float4 bv = *(const float4*)&b[tid * 4];
    float4 o4;
    o4.x = (v.x - mu) * inv * gv.x + bv.x;
    o4.y = (v.y - mu) * inv * gv.y + bv.y;
    o4.z = (v.z - mu) * inv * gv.z + bv.z;
    o4.w = (v.w - mu) * inv * gv.w + bv.w;
    *(float4*)&out[(size_t)row * Dq + tid * 4] = o4;
}

// ---------------- RoPE in place on q and k parts of g_qkv -------------------
__global__ void __launch_bounds__(256) rope_kernel(const float* __restrict__ freqs) {
    int idx = blockIdx.x * blockDim.x + threadIdx.x;   // over L*H*32
    if (idx >= Lq * Hq * (HDq / 2)) return;
    int t = idx & 31;
    int h = (idx >> 5) & 15;
    int l = idx >> 9;
    float c = freqs[((size_t)l * 32 + t) * 2 + 0];
    float s = freqs[((size_t)l * 32 + t) * 2 + 1];
    #pragma unroll
    for (int part = 0; part < 2; part++) {
        float* p = &g_qkv[(size_t)l * (3 * Dq) + part * Dq + h * HDq + 2 * t];
        float a = p[0], bb = p[1];
        p[0] = a * c - bb * s;
        p[1] = a * s + bb * c;
    }
}

// ---------------- GELU (exact) ----------------------------------------------
__device__ __forceinline__ float gelu_exact(float x) {
    return 0.5f * x * (1.0f + erff(x * 0.70710678118654752f));
}

// ---------------- tf32 helpers ----------------------------------------------
__device__ __forceinline__ float to_tf32(float x) {
    uint32_t u;
    asm("cvt.rna.tf32.f32 %0, %1;" : "=r"(u) : "f"(x));
    return __uint_as_float(u);
}

__device__ __forceinline__ void mma_tf32(float* d, const uint32_t* a, const uint32_t* b) {
    asm volatile(
        "mma.sync.aligned.m16n8k8.row.col.f32.tf32.tf32.f32 "
        "{%0,%1,%2,%3}, {%4,%5,%6,%7}, {%8,%9}, {%0,%1,%2,%3};"
        : "+f"(d[0]), "+f"(d[1]), "+f"(d[2]), "+f"(d[3])
        : "r"(a[0]), "r"(a[1]), "r"(a[2]), "r"(a[3]), "r"(b[0]), "r"(b[1]));
}

// ---------------- TF32 tensor-core GEMM 128x128, BK=16, 256 threads ---------
// Warp layout: 2 (M) x 4 (N) warps; warp tile 64x32 = 4 mtiles x 4 ntiles of
// m16n8k8 fragments. Double-buffered smem, pad 136 floats (8-bank row stride:
// fragment LDS bank = 8*kgroup + mgroup, conflict-free).
// EPI: 0 = none, 1 = +bias then gelu, 2 = +res, 3 = +bias +res
template <int EPI>
__global__ void __launch_bounds__(256) tgemm(const float* __restrict__ A,
                                             const float* __restrict__ B,
                                             const float* __restrict__ bias,
                                             const float* __restrict__ res,
                                             float* __restrict__ C,
                                             int N, int K) {
    __shared__ float As[2][16][136];
    __shared__ float Bs[2][16][136];

    const int tid  = threadIdx.x;
    const int warp = tid >> 5, lane = tid & 31;
    const int gid  = lane >> 2, tig = lane & 3;
    const int wm   = warp >> 2, wn = warp & 3;    // 2 x 4 warps
    const int m_w  = wm * 64,   n_w = wn * 32;
    const int bm   = blockIdx.y, bn = blockIdx.x;

    // gmem load mapping
    const int arow = tid >> 2;                    // 0..63 (and +64)
    const int akq  = (tid & 3) * 4;               // k offset 0/4/8/12
    const int bkr  = tid >> 5;                    // 0..7 (and +8)
    const int bnq  = (tid & 31) * 4;              // n offset 0..124

    const float* Ag = A + (size_t)(bm * 128 + arow) * K + akq;
    const float* Bg = B + (size_t)bkr * N + bn * 128 + bnq;

    float acc[4][4][4];
    #pragma unroll
    for (int i = 0; i < 4; i++)
        #pragma unroll
        for (int j = 0; j < 4; j++)
            #pragma unroll
            for (int c = 0; c < 4; c++) acc[i][j][c] = 0.f;

    // prologue: stage 0
    {
        float4 a0 = *(const float4*)(Ag);
        float4 a1 = *(const float4*)(Ag + (size_t)64 * K);
        float4 b0 = *(const float4*)(Bg);
        float4 b1 = *(const float4*)(Bg + (size_t)8 * N);
        As[0][akq + 0][arow] = to_tf32(a0.x);
        As[0][akq + 1][arow] = to_tf32(a0.y);
        As[0][akq + 2][arow] = to_tf32(a0.z);
        As[0][akq + 3][arow] = to_tf32(a0.w);
        As[0][akq + 0][arow + 64] = to_tf32(a1.x);
        As[0][akq + 1][arow + 64] = to_tf32(a1.y);
        As[0][akq + 2][arow + 64] = to_tf32(a1.z);
        As[0][akq + 3][arow + 64] = to_tf32(a1.w);
        float4 t0 = make_float4(to_tf32(b0.x), to_tf32(b0.y), to_tf32(b0.z), to_tf32(b0.w));
        float4 t1 = make_float4(to_tf32(b1.x), to_tf32(b1.y), to_tf32(b1.z), to_tf32(b1.w));
        *(float4*)&Bs[0][bkr][bnq]     = t0;
        *(float4*)&Bs[0][bkr + 8][bnq] = t1;
    }
    __syncthreads();

    for (int k0 = 0; k0 < K; k0 += 16) {
        const int buf = (k0 >> 4) & 1;
        const bool has_next = (k0 + 16) < K;

        float4 a0, a1, b0, b1;
        if (has_next) {
            a0 = *(const float4*)(Ag + k0 + 16);
            a1 = *(const float4*)(Ag + (size_t)64 * K + k0 + 16);
            b0 = *(const float4*)(Bg + (size_t)(k0 + 16) * N);
            b1 = *(const float4*)(Bg + (size_t)(k0 + 24) * N);
        }

        #pragma unroll
        for (int kk = 0; kk < 16; kk += 8) {
            uint32_t afr[4][4];
            #pragma unroll
            for (int mt = 0; mt < 4; mt++) {
                int r0 = m_w + mt * 16 + gid;
                afr[mt][0] = __float_as_uint(As[buf][kk + tig][r0]);
                afr[mt][1] = __float_as_uint(As[buf][kk + tig][r0 + 8]);
                afr[mt][2] = __float_as_uint(As[buf][kk + tig + 4][r0]);
                afr[mt][3] = __float_as_uint(As[buf][kk + tig + 4][r0 + 8]);
            }
            uint32_t bfr[4][2];
            #pragma unroll
            for (int nt = 0; nt < 4; nt++) {
                int c0 = n_w + nt * 8 + gid;
                bfr[nt][0] = __float_as_uint(Bs[buf][kk + tig][c0]);
                bfr[nt][1] = __float_as_uint(Bs[buf][kk + tig + 4][c0]);
            }
            #pragma unroll
            for (int mt = 0; mt < 4; mt++)
                #pragma unroll
                for (int nt = 0; nt < 4; nt++)
                    mma_tf32(acc[mt][nt], afr[mt], bfr[nt]);
        }

        if (has_next) {
            const int nb = buf ^ 1;
            As[nb][akq + 0][arow] = to_tf32(a0.x);
            As[nb][akq + 1][arow] = to_tf32(a0.y);
            As[nb][akq + 2][arow] = to_tf32(a0.z);
            As[nb][akq + 3][arow] = to_tf32(a0.w);
            As[nb][akq + 0][arow + 64] = to_tf32(a1.x);
            As[nb][akq + 1][arow + 64] = to_tf32(a1.y);
            As[nb][akq + 2][arow + 64] = to_tf32(a1.z);
            As[nb][akq + 3][arow + 64] = to_tf32(a1.w);
            float4 t0 = make_float4(to_tf32(b0.x), to_tf32(b0.y), to_tf32(b0.z), to_tf32(b0.w));
            float4 t1 = make_float4(to_tf32(b1.x), to_tf32(b1.y), to_tf32(b1.z), to_tf32(b1.w));
            *(float4*)&Bs[nb][bkr][bnq]     = t0;
            *(float4*)&Bs[nb][bkr + 8][bnq] = t1;
        }
        __syncthreads();
    }

    // epilogue: d0/d1 -> (row, col), (row, col+1); d2/d3 -> (row+8, ...)
    #pragma unroll
    for (int mt = 0; mt < 4; mt++) {
        int row0 = bm * 128 + m_w + mt * 16 + gid;
        #pragma unroll
        for (int nt = 0; nt < 4; nt++) {
            int col = bn * 128 + n_w + nt * 8 + tig * 2;
            #pragma unroll
            for (int half = 0; half < 2; half++) {
                int row = row0 + half * 8;
                float r0 = acc[mt][nt][half * 2 + 0];
                float r1 = acc[mt][nt][half * 2 + 1];
                if (EPI == 1 || EPI == 3) {
                    r0 += bias[col];
                    r1 += bias[col + 1];
                }
                if (EPI == 1) { r0 = gelu_exact(r0); r1 = gelu_exact(r1); }
                size_t base = (size_t)row * N + col;
                if (EPI == 2 || EPI == 3) {
                    float2 rv = *(const float2*)&res[base];
                    r0 += rv.x; r1 += rv.y;
                }
                float2 o2 = make_float2(r0, r1);
                *(float2*)&C[base] = o2;
            }
        }
    }
}

// ---------------- Attention: flash-style, 1 q-row per thread ----------------
__global__ void __launch_bounds__(64) attn_kernel() {
    int qt   = blockIdx.x;
    int head = blockIdx.y;
    int seg  = blockIdx.z;
    int tid  = threadIdx.x;
    int qrow = seg * 1024 + qt * 64 + tid;

    __shared__ float Ks[64][64];
    __shared__ float Vs[64][64];

    const float scale = 0.125f;  // 1/sqrt(64)
    float q[64];
    {
        const float* qp = &g_qkv[(size_t)qrow * (3 * Dq) + head * HDq];
        #pragma unroll
        for (int d = 0; d < 64; d += 4) {
            float4 v = *(const float4*)&qp[d];
            q[d] = v.x * scale; q[d + 1] = v.y * scale;
            q[d + 2] = v.z * scale; q[d + 3] = v.w * scale;
        }
    }

    float o[64];
    #pragma unroll
    for (int d = 0; d < 64; d++) o[d] = 0.f;
    float m = -1e30f, lsum = 0.f;

    for (int kc = 0; kc < 16; kc++) {
        __syncthreads();
        for (int idx = tid; idx < 64 * 64; idx += 64) {
            int r = idx >> 6, d = idx & 63;
            size_t base = (size_t)(seg * 1024 + kc * 64 + r) * (3 * Dq) + head * HDq + d;
            Ks[r][d] = g_qkv[base + Dq];
            Vs[r][d] = g_qkv[base + 2 * Dq];
        }
        __syncthreads();

        float s[64];
        float mc = -1e30f;
        #pragma unroll
        for (int j = 0; j < 64; j++) {
            float a = 0.f;
            #pragma unroll
            for (int d = 0; d < 64; d += 4) {
                float4 kv = *(const float4*)&Ks[j][d];
                a += q[d] * kv.x + q[d + 1] * kv.y + q[d + 2] * kv.z + q[d + 3] * kv.w;
            }
            s[j] = a;
            mc = fmaxf(mc, a);
        }
        float mnew = fmaxf(m, mc);
        float corr = __expf(m - mnew);
        m = mnew;
        lsum *= corr;
        #pragma unroll
        for (int d = 0; d < 64; d++) o[d] *= corr;
        #pragma unroll
        for (int j = 0; j < 64; j++) {
            float p = __expf(s[j] - mnew);
            lsum += p;
            #pragma unroll
            for (int d = 0; d < 64; d += 4) {
                float4 vv = *(const float4*)&Vs[j][d];
                o[d]     += p * vv.x;
                o[d + 1] += p * vv.y;
                o[d + 2] += p * vv.z;
                o[d + 3] += p * vv.w;
            }
        }
    }

    float inv = 1.0f / lsum;
    float* op = &g_attn[(size_t)qrow * Dq + head * HDq];
    #pragma unroll
    for (int d = 0; d < 64; d += 4) {
        float4 o4 = make_float4(o[d] * inv, o[d + 1] * inv, o[d + 2] * inv, o[d + 3] * inv);
        *(float4*)&op[d] = o4;
    }
}

// ---------------- host orchestration ---------------------------------------
extern "C" void kernel_launch(void* const* d_in, const int* in_sizes, int n_in,
                              void* d_out, int out_size) {
    const float* hidden = (const float*)d_in[0];
    // d_in[1] = cu_seqlens (fixed [0,1024,2048,3072,4096]); segments hardcoded
    const float* rope   = (const float*)d_in[2];
    const float* ln0_g  = (const float*)d_in[3];
    const float* ln0_b  = (const float*)d_in[4];
    const float* ln1_g  = (const float*)d_in[5];
    const float* ln1_b  = (const float*)d_in[6];
    const float* w_qkv  = (const float*)d_in[7];
    const float* w_o    = (const float*)d_in[8];
    const float* w_fc0  = (const float*)d_in[9];
    const float* b_fc0  = (const float*)d_in[10];
    const float* w_fc1  = (const float*)d_in[11];
    const float* b_fc1  = (const float*)d_in[12];
    float* out = (float*)d_out;

    float *p_xln, *p_qkv, *p_attn, *p_h, *p_yln, *p_fc0;
    cudaGetSymbolAddress((void**)&p_xln,  g_xln);
    cudaGetSymbolAddress((void**)&p_qkv,  g_qkv);
    cudaGetSymbolAddress((void**)&p_attn, g_attn);
    cudaGetSymbolAddress((void**)&p_h,    g_h);
    cudaGetSymbolAddress((void**)&p_yln,  g_yln);
    cudaGetSymbolAddress((void**)&p_fc0,  g_fc0);

    // 1. LN0
    ln_kernel<<<Lq, 256>>>(hidden, ln0_g, ln0_b, p_xln);

    // 2. QKV = xln @ w_qkv   [4096 x 3072], K=1024
    tgemm<0><<<dim3(3 * Dq / 128, Lq / 128), 256>>>(p_xln, w_qkv, nullptr, nullptr,
                                                    p_qkv, 3 * Dq, Dq);
    // 3. RoPE in place on q,k
    rope_kernel<<<(Lq * Hq * 32) / 256, 256>>>(rope);

    // 4. Attention (block-diagonal, 4 segments of 1024)
    attn_kernel<<<dim3(16, Hq, 4), 64>>>();

    // 5. h = hidden + attn @ w_o   [4096 x 1024], K=1024
    tgemm<2><<<dim3(Dq / 128, Lq / 128), 256>>>(p_attn, w_o, nullptr, hidden,
                                                p_h, Dq, Dq);
    // 6. LN1
    ln_kernel<<<Lq, 256>>>(p_h, ln1_g, ln1_b, p_yln);

    // 7. fc0 + bias + gelu   [4096 x 4096], K=1024
    tgemm<1><<<dim3(Mq / 128, Lq / 128), 256>>>(p_yln, w_fc0, b_fc0, nullptr,
                                                p_fc0, Mq, Dq);
    // 8. out = h + fc0g @ w_fc1 + b_fc1   [4096 x 1024], K=4096
    tgemm<3><<<dim3(Dq / 128, Lq / 128), 256>>>(p_fc0, w_fc1, b_fc1, p_h,
                                                out, Dq, Mq);
    (void)in_sizes; (void)n_in; (void)out_size;
}

// round 3
// speedup vs baseline: 3.7183x; 2.1326x over previous
#include <cuda_runtime.h>
#include <math.h>
#include <stdint.h>

#define Lq 4096
#define Dq 1024
#define Hq 16
#define HDq 64
#define Mq 4096

// ---------------- scratch (device globals; no allocation allowed) ----------
__device__ float g_xln [Lq*Dq];
__device__ float g_qkv [Lq*3*Dq];
__device__ float g_attn[Lq*Dq];
__device__ float g_h   [Lq*Dq];
__device__ float g_yln [Lq*Dq];
__device__ float g_fc0 [(size_t)Lq*Mq];

// ---------------- async copy helpers ----------------------------------------
__device__ __forceinline__ void cp16(uint32_t dst, const void* src) {
    asm volatile("cp.async.cg.shared.global [%0], [%1], 16;" :: "r"(dst), "l"(src));
}
#define CP_COMMIT() asm volatile("cp.async.commit_group;" ::: "memory")
#define CP_WAIT2()  asm volatile("cp.async.wait_group 2;" ::: "memory")

__device__ __forceinline__ float to_tf32(float x) {
    uint32_t u;
    asm("cvt.rna.tf32.f32 %0, %1;" : "=r"(u) : "f"(x));
    return __uint_as_float(u);
}

__device__ __forceinline__ void mma_tf32(float* d, const uint32_t* a, const uint32_t* b) {
    asm volatile(
        "mma.sync.aligned.m16n8k8.row.col.f32.tf32.tf32.f32 "
        "{%0,%1,%2,%3}, {%4,%5,%6,%7}, {%8,%9}, {%0,%1,%2,%3};"
        : "+f"(d[0]), "+f"(d[1]), "+f"(d[2]), "+f"(d[3])
        : "r"(a[0]), "r"(a[1]), "r"(a[2]), "r"(a[3]), "r"(b[0]), "r"(b[1]));
}

// ---------------- LayerNorm --------------------------------------------------
__global__ void __launch_bounds__(256) ln_kernel(const float* __restrict__ x,
                                                 const float* __restrict__ g,
                                                 const float* __restrict__ b,
                                                 float* __restrict__ out) {
    int row = blockIdx.x;
    int tid = threadIdx.x;
    const float* xr = x + (size_t)row * Dq;
    float4 v = *(const float4*)&xr[tid * 4];
    float sum = v.x + v.y + v.z + v.w;
    float sq  = v.x*v.x + v.y*v.y + v.z*v.z + v.w*v.w;
    #pragma unroll
    for (int o = 16; o; o >>= 1) {
        sum += __shfl_xor_sync(0xffffffffu, sum, o);
        sq  += __shfl_xor_sync(0xffffffffu, sq,  o);
    }
    __shared__ float red0[8], red1[8];
    int wid = tid >> 5, lane = tid & 31;
    if (lane == 0) { red0[wid] = sum; red1[wid] = sq; }
    __syncthreads();
    float tot = 0.f, totq = 0.f;
    #pragma unroll
    for (int i = 0; i < 8; i++) { tot += red0[i]; totq += red1[i]; }
    float mu  = tot * (1.0f / Dq);
    float var = totq * (1.0f / Dq) - mu * mu;
    float inv = rsqrtf(var + 1e-5f);
    float4 gv = *(const float4*)&g[tid * 4];
    float4 bv = *(const float4*)&b[tid * 4];
    float4 o4;
    o4.x = (v.x - mu) * inv * gv.x + bv.x;
    o4.y = (v.y - mu) * inv * gv.y + bv.y;
    o4.z = (v.z - mu) * inv * gv.z + bv.z;
    o4.w = (v.w - mu) * inv * gv.w + bv.w;
    *(float4*)&out[(size_t)row * Dq + tid * 4] = o4;
}

// ---------------- RoPE in place on q and k parts of g_qkv -------------------
__global__ void __launch_bounds__(256) rope_kernel(const float* __restrict__ freqs) {
    int idx = blockIdx.x * blockDim.x + threadIdx.x;
    if (idx >= Lq * Hq * (HDq / 2)) return;
    int t = idx & 31;
    int h = (idx >> 5) & 15;
    int l = idx >> 9;
    float c = freqs[((size_t)l * 32 + t) * 2 + 0];
    float s = freqs[((size_t)l * 32 + t) * 2 + 1];
    #pragma unroll
    for (int part = 0; part < 2; part++) {
        float* p = &g_qkv[(size_t)l * (3 * Dq) + part * Dq + h * HDq + 2 * t];
        float a = p[0], bb = p[1];
        p[0] = a * c - bb * s;
        p[1] = a * s + bb * c;
    }
}

__device__ __forceinline__ float gelu_exact(float x) {
    return 0.5f * x * (1.0f + erff(x * 0.70710678118654752f));
}

// ---------------- TF32 GEMM: 128x128 tile, BK=16, 4-stage cp.async ----------
// smem: As[4][128][20] then Bs[4][16][132] (floats). Raw fp32 fed to mma
// (HW truncates to tf32). EPI: 0 none, 1 bias+gelu, 2 +res, 3 bias+res.
#define GEMM_SMEM_FLOATS (4*128*20 + 4*16*132)
template <int EPI>
__global__ void __launch_bounds__(256) tgemm(const float* __restrict__ A,
                                             const float* __restrict__ B,
                                             const float* __restrict__ bias,
                                             const float* __restrict__ res,
                                             float* __restrict__ C,
                                             int N, int K) {
    extern __shared__ float sm[];
    const int tid  = threadIdx.x;
    const int warp = tid >> 5, lane = tid & 31;
    const int gid  = lane >> 2, tig = lane & 3;
    const int wm   = warp >> 2, wn = warp & 3;
    const int m_w  = wm * 64,   n_w = wn * 32;
    const int bm   = blockIdx.y, bn = blockIdx.x;

    // cp.async source pointers
    const int arow = tid >> 2;                 // 0..63 (and +64)
    const int aoff = (tid & 3) * 4;
    const int brow = tid >> 5;                 // 0..7 (and +8)
    const int boff = (tid & 31) * 4;
    const float* Ag = A + (size_t)(bm * 128 + arow) * K + aoff;
    const float* Bg = B + (size_t)brow * N + bn * 128 + boff;

    // per-stage smem dst addresses
    uint32_t dA0[4], dA1[4], dB0[4], dB1[4];
    #pragma unroll
    for (int s = 0; s < 4; s++) {
        dA0[s] = (uint32_t)__cvta_generic_to_shared(&sm[s*2560 + arow*20 + aoff]);
        dA1[s] = dA0[s] + 64*20*4;
        dB0[s] = (uint32_t)__cvta_generic_to_shared(&sm[10240 + s*2112 + brow*132 + boff]);
        dB1[s] = dB0[s] + 8*132*4;
    }

    float acc[4][4][4];
    #pragma unroll
    for (int i = 0; i < 4; i++)
        #pragma unroll
        for (int j = 0; j < 4; j++)
            #pragma unroll
            for (int c = 0; c < 4; c++) acc[i][j][c] = 0.f;

    const int niter = K >> 4;
    // prologue: stages 0,1,2
    #pragma unroll
    for (int s = 0; s < 3; s++) {
        int k0 = s * 16;
        cp16(dA0[s], Ag + k0);
        cp16(dA1[s], Ag + (size_t)64 * K + k0);
        cp16(dB0[s], Bg + (size_t)k0 * N);
        cp16(dB1[s], Bg + (size_t)(k0 + 8) * N);
        CP_COMMIT();
    }

    for (int kt = 0; kt < niter; kt++) {
        CP_WAIT2();
        __syncthreads();
        const int s = kt & 3;
        if (kt + 3 < niter) {
            const int sn = (kt + 3) & 3;
            const int k0 = (kt + 3) << 4;
            cp16(dA0[sn], Ag + k0);
            cp16(dA1[sn], Ag + (size_t)64 * K + k0);
            cp16(dB0[sn], Bg + (size_t)k0 * N);
            cp16(dB1[sn], Bg + (size_t)(k0 + 8) * N);
        }
        CP_COMMIT();

        const float* As_ = sm + s * 2560;
        const float* Bs_ = sm + 10240 + s * 2112;
        #pragma unroll
        for (int kk = 0; kk < 16; kk += 8) {
            uint32_t afr[4][4];
            #pragma unroll
            for (int mt = 0; mt < 4; mt++) {
                int r0 = m_w + mt * 16 + gid;
                afr[mt][0] = __float_as_uint(As_[r0 * 20 + kk + tig]);
                afr[mt][1] = __float_as_uint(As_[(r0 + 8) * 20 + kk + tig]);
                afr[mt][2] = __float_as_uint(As_[r0 * 20 + kk + tig + 4]);
                afr[mt][3] = __float_as_uint(As_[(r0 + 8) * 20 + kk + tig + 4]);
            }
            uint32_t bfr[4][2];
            #pragma unroll
            for (int nt = 0; nt < 4; nt++) {
                int c0 = n_w + nt * 8 + gid;
                bfr[nt][0] = __float_as_uint(Bs_[(kk + tig) * 132 + c0]);
                bfr[nt][1] = __float_as_uint(Bs_[(kk + tig + 4) * 132 + c0]);
            }
            #pragma unroll
            for (int mt = 0; mt < 4; mt++)
                #pragma unroll
                for (int nt = 0; nt < 4; nt++)
                    mma_tf32(acc[mt][nt], afr[mt], bfr[nt]);
        }
    }

    #pragma unroll
    for (int mt = 0; mt < 4; mt++) {
        int row0 = bm * 128 + m_w + mt * 16 + gid;
        #pragma unroll
        for (int nt = 0; nt < 4; nt++) {
            int col = bn * 128 + n_w + nt * 8 + tig * 2;
            #pragma unroll
            for (int half = 0; half < 2; half++) {
                int row = row0 + half * 8;
                float r0 = acc[mt][nt][half * 2 + 0];
                float r1 = acc[mt][nt][half * 2 + 1];
                if (EPI == 1 || EPI == 3) {
                    r0 += bias[col];
                    r1 += bias[col + 1];
                }
                if (EPI == 1) { r0 = gelu_exact(r0); r1 = gelu_exact(r1); }
                size_t base = (size_t)row * N + col;
                if (EPI == 2 || EPI == 3) {
                    float2 rv = *(const float2*)&res[base];
                    r0 += rv.x; r1 += rv.y;
                }
                float2 o2 = make_float2(r0, r1);
                *(float2*)&C[base] = o2;
            }
        }
    }
}

// ---------------- Attention: tensor-core flash, 128 q-rows / block ---------
// grid (8 qtiles, 16 heads, 4 segs), 256 threads (8 warps x 16 q-rows).
// smem: Ks[64][68], Vs[64][68] natural [key][d] layout (fragment indexing
// swaps roles for the QK B-operand), Ps[128][68] for C-frag -> A-frag route.
#define ATTN_SMEM_FLOATS (64*68*2 + 128*68)
__global__ void __launch_bounds__(256) attn_kernel() {
    extern __shared__ float sm[];
    float* Ks = sm;
    float* Vs = sm + 64 * 68;
    float* Ps = sm + 2 * 64 * 68;

    const int qt = blockIdx.x, head = blockIdx.y, seg = blockIdx.z;
    const int tid = threadIdx.x, warp = tid >> 5, lane = tid & 31;
    const int gid = lane >> 2, tig = lane & 3;
    const int q0 = seg * 1024 + qt * 128;
    const int wrow = warp * 16;
    const float scale = 0.125f;

    // Q fragments, resident for whole block
    uint32_t qf[8][4];
    {
        const float* Q0 = g_qkv + (size_t)(q0 + wrow + gid) * (3 * Dq) + head * HDq;
        const float* Q1 = Q0 + (size_t)8 * (3 * Dq);
        #pragma unroll
        for (int kk = 0; kk < 8; kk++) {
            qf[kk][0] = __float_as_uint(to_tf32(Q0[kk * 8 + tig] * scale));
            qf[kk][1] = __float_as_uint(to_tf32(Q1[kk * 8 + tig] * scale));
            qf[kk][2] = __float_as_uint(to_tf32(Q0[kk * 8 + tig + 4] * scale));
            qf[kk][3] = __float_as_uint(to_tf32(Q1[kk * 8 + tig + 4] * scale));
        }
    }

    float o[8][4];
    #pragma unroll
    for (int nt = 0; nt < 8; nt++)
        #pragma unroll
        for (int j = 0; j < 4; j++) o[nt][j] = 0.f;
    float m0 = -1e30f, m1 = -1e30f, l0 = 0.f, l1 = 0.f;

    for (int ch = 0; ch < 16; ch++) {
        __syncthreads();
        #pragma unroll
        for (int i = 0; i < 4; i++) {
            int lin = i * 256 + tid;
            int key = lin >> 4;
            int d4  = (lin & 15) * 4;
            const float* base = g_qkv + (size_t)(seg * 1024 + ch * 64 + key) * (3 * Dq)
                              + head * HDq + d4;
            float4 k4 = *(const float4*)(base + Dq);
            float4 v4 = *(const float4*)(base + 2 * Dq);
            float4 kt = make_float4(to_tf32(k4.x), to_tf32(k4.y), to_tf32(k4.z), to_tf32(k4.w));
            float4 vt = make_float4(to_tf32(v4.x), to_tf32(v4.y), to_tf32(v4.z), to_tf32(v4.w));
            *(float4*)&Ks[key * 68 + d4] = kt;
            *(float4*)&Vs[key * 68 + d4] = vt;
        }
        __syncthreads();

        // S = Q * K^T  (per-warp 16x64 tile)
        float s[8][4];
        #pragma unroll
        for (int nt = 0; nt < 8; nt++)
            #pragma unroll
            for (int j = 0; j < 4; j++) s[nt][j] = 0.f;
        #pragma unroll
        for (int kk = 0; kk < 8; kk++) {
            #pragma unroll
            for (int nt = 0; nt < 8; nt++) {
                uint32_t bb[2];
                bb[0] = __float_as_uint(Ks[(nt * 8 + gid) * 68 + kk * 8 + tig]);
                bb[1] = __float_as_uint(Ks[(nt * 8 + gid) * 68 + kk * 8 + tig + 4]);
                mma_tf32(s[nt], qf[kk], bb);
            }
        }

        // online softmax (rows gid and gid+8)
        float mc0 = -1e30f, mc1 = -1e30f;
        #pragma unroll
        for (int nt = 0; nt < 8; nt++) {
            mc0 = fmaxf(mc0, fmaxf(s[nt][0], s[nt][1]));
            mc1 = fmaxf(mc1, fmaxf(s[nt][2], s[nt][3]));
        }
        mc0 = fmaxf(mc0, __shfl_xor_sync(0xffffffffu, mc0, 1));
        mc0 = fmaxf(mc0, __shfl_xor_sync(0xffffffffu, mc0, 2));
        mc1 = fmaxf(mc1, __shfl_xor_sync(0xffffffffu, mc1, 1));
        mc1 = fmaxf(mc1, __shfl_xor_sync(0xffffffffu, mc1, 2));
        float mn0 = fmaxf(m0, mc0), mn1 = fmaxf(m1, mc1);
        float c0 = __expf(m0 - mn0), c1 = __expf(m1 - mn1);
        m0 = mn0; m1 = mn1;
        l0 *= c0;  l1 *= c1;
        #pragma unroll
        for (int nt = 0; nt < 8; nt++) {
            o[nt][0] *= c0; o[nt][1] *= c0;
            o[nt][2] *= c1; o[nt][3] *= c1;
        }
        #pragma unroll
        for (int nt = 0; nt < 8; nt++) {
            float p0 = to_tf32(__expf(s[nt][0] - mn0));
            float p1 = to_tf32(__expf(s[nt][1] - mn0));
            float p2 = to_tf32(__expf(s[nt][2] - mn1));
            float p3 = to_tf32(__expf(s[nt][3] - mn1));
            l0 += p0 + p1;
            l1 += p2 + p3;
            *(float2*)&Ps[(wrow + gid) * 68 + nt * 8 + tig * 2]     = make_float2(p0, p1);
            *(float2*)&Ps[(wrow + gid + 8) * 68 + nt * 8 + tig * 2] = make_float2(p2, p3);
        }
        __syncwarp();

        // O += P * V
        #pragma unroll
        for (int kk = 0; kk < 8; kk++) {
            uint32_t af[4];
            af[0] = __float_as_uint(Ps[(wrow + gid) * 68 + kk * 8 + tig]);
            af[1] = __float_as_uint(Ps[(wrow + gid + 8) * 68 + kk * 8 + tig]);
            af[2] = __float_as_uint(Ps[(wrow + gid) * 68 + kk * 8 + tig + 4]);
            af[3] = __float_as_uint(Ps[(wrow + gid + 8) * 68 + kk * 8 + tig + 4]);
            #pragma unroll
            for (int nt = 0; nt < 8; nt++) {
                uint32_t bb[2];
                bb[0] = __float_as_uint(Vs[(kk * 8 + tig) * 68 + nt * 8 + gid]);
                bb[1] = __float_as_uint(Vs[(kk * 8 + tig + 4) * 68 + nt * 8 + gid]);
                mma_tf32(o[nt], af, bb);
            }
        }
    }

    l0 += __shfl_xor_sync(0xffffffffu, l0, 1);
    l0 += __shfl_xor_sync(0xffffffffu, l0, 2);
    l1 += __shfl_xor_sync(0xffffffffu, l1, 1);
    l1 += __shfl_xor_sync(0xffffffffu, l1, 2);
    float inv0 = 1.0f / l0, inv1 = 1.0f / l1;

    float* O0 = g_attn + (size_t)(q0 + wrow + gid) * Dq + head * HDq;
    float* O1 = O0 + (size_t)8 * Dq;
    #pragma unroll
    for (int nt = 0; nt < 8; nt++) {
        *(float2*)&O0[nt * 8 + tig * 2] = make_float2(o[nt][0] * inv0, o[nt][1] * inv0);
        *(float2*)&O1[nt * 8 + tig * 2] = make_float2(o[nt][2] * inv1, o[nt][3] * inv1);
    }
}

// ---------------- host orchestration ---------------------------------------
extern "C" void kernel_launch(void* const* d_in, const int* in_sizes, int n_in,
                              void* d_out, int out_size) {
    const float* hidden = (const float*)d_in[0];
    const float* rope   = (const float*)d_in[2];
    const float* ln0_g  = (const float*)d_in[3];
    const float* ln0_b  = (const float*)d_in[4];
    const float* ln1_g  = (const float*)d_in[5];
    const float* ln1_b  = (const float*)d_in[6];
    const float* w_qkv  = (const float*)d_in[7];
    const float* w_o    = (const float*)d_in[8];
    const float* w_fc0  = (const float*)d_in[9];
    const float* b_fc0  = (const float*)d_in[10];
    const float* w_fc1  = (const float*)d_in[11];
    const float* b_fc1  = (const float*)d_in[12];
    float* out = (float*)d_out;

    float *p_xln, *p_qkv, *p_attn, *p_h, *p_yln, *p_fc0;
    cudaGetSymbolAddress((void**)&p_xln,  g_xln);
    cudaGetSymbolAddress((void**)&p_qkv,  g_qkv);
    cudaGetSymbolAddress((void**)&p_attn, g_attn);
    cudaGetSymbolAddress((void**)&p_h,    g_h);
    cudaGetSymbolAddress((void**)&p_yln,  g_yln);
    cudaGetSymbolAddress((void**)&p_fc0,  g_fc0);

    const int gemm_smem = GEMM_SMEM_FLOATS * 4;
    const int attn_smem = ATTN_SMEM_FLOATS * 4;
    cudaFuncSetAttribute(tgemm<0>, cudaFuncAttributeMaxDynamicSharedMemorySize, gemm_smem);
    cudaFuncSetAttribute(tgemm<1>, cudaFuncAttributeMaxDynamicSharedMemorySize, gemm_smem);
    cudaFuncSetAttribute(tgemm<2>, cudaFuncAttributeMaxDynamicSharedMemorySize, gemm_smem);
    cudaFuncSetAttribute(tgemm<3>, cudaFuncAttributeMaxDynamicSharedMemorySize, gemm_smem);
    cudaFuncSetAttribute(attn_kernel, cudaFuncAttributeMaxDynamicSharedMemorySize, attn_smem);

    // 1. LN0
    ln_kernel<<<Lq, 256>>>(hidden, ln0_g, ln0_b, p_xln);
    // 2. QKV
    tgemm<0><<<dim3(3 * Dq / 128, Lq / 128), 256, gemm_smem>>>(p_xln, w_qkv, nullptr, nullptr,
                                                               p_qkv, 3 * Dq, Dq);
    // 3. RoPE
    rope_kernel<<<(Lq * Hq * 32) / 256, 256>>>(rope);
    // 4. Attention
    attn_kernel<<<dim3(8, Hq, 4), 256, attn_smem>>>();
    // 5. h = hidden + attn @ w_o
    tgemm<2><<<dim3(Dq / 128, Lq / 128), 256, gemm_smem>>>(p_attn, w_o, nullptr, hidden,
                                                           p_h, Dq, Dq);
    // 6. LN1
    ln_kernel<<<Lq, 256>>>(p_h, ln1_g, ln1_b, p_yln);
    // 7. fc0 + bias + gelu
    tgemm<1><<<dim3(Mq / 128, Lq / 128), 256, gemm_smem>>>(p_yln, w_fc0, b_fc0, nullptr,
                                                           p_fc0, Mq, Dq);
    // 8. out = h + fc0g @ w_fc1 + b_fc1
    tgemm<3><<<dim3(Dq / 128, Lq / 128), 256, gemm_smem>>>(p_fc0, w_fc1, b_fc1, p_h,
                                                           out, Dq, Mq);
    (void)in_sizes; (void)n_in; (void)out_size;
}

// round 5
// speedup vs baseline: 5.6901x; 1.5303x over previous
#include <cuda_runtime.h>
#include <cuda_fp16.h>
#include <math.h>
#include <stdint.h>

#define Lq 4096
#define Dq 1024
#define Hq 16
#define HDq 64
#define Mq 4096

// ---------------- scratch (device globals; no allocation allowed) ----------
__device__ float  g_qkv  [Lq*3*Dq];          // fp32 qkv (rope applied in place)
__device__ float  g_h    [Lq*Dq];            // fp32 residual+attn@w_o
// half activations (GEMM A operands)
__device__ __half g_xlnh [Lq*Dq];
__device__ __half g_ylnh [Lq*Dq];
__device__ __half g_attnh[Lq*Dq];
__device__ __half g_fc0h [(size_t)Lq*Mq];
// half transposed weights [N][K]
__device__ __half g_wqkvT[3*Dq*Dq];
__device__ __half g_woT  [Dq*Dq];
__device__ __half g_fc0T [(size_t)Mq*Dq];
__device__ __half g_fc1T [(size_t)Dq*Mq];

// ---------------- helpers ----------------------------------------------------
__device__ __forceinline__ void cp16(uint32_t dst, const void* src) {
    asm volatile("cp.async.cg.shared.global [%0], [%1], 16;" :: "r"(dst), "l"(src));
}
#define CP_COMMIT() asm volatile("cp.async.commit_group;" ::: "memory")
#define CP_WAIT2()  asm volatile("cp.async.wait_group 2;" ::: "memory")

__device__ __forceinline__ uint32_t packh(float a, float b) {
    __half2 h = __floats2half2_rn(a, b);
    return *(uint32_t*)&h;
}
__device__ __forceinline__ void mma_f16(float* d, const uint32_t* a, const uint32_t* b) {
    asm volatile(
        "mma.sync.aligned.m16n8k16.row.col.f32.f16.f16.f32 "
        "{%0,%1,%2,%3}, {%4,%5,%6,%7}, {%8,%9}, {%0,%1,%2,%3};"
        : "+f"(d[0]), "+f"(d[1]), "+f"(d[2]), "+f"(d[3])
        : "r"(a[0]), "r"(a[1]), "r"(a[2]), "r"(a[3]), "r"(b[0]), "r"(b[1]));
}

__device__ __forceinline__ float gelu_exact(float x) {
    return 0.5f * x * (1.0f + erff(x * 0.70710678118654752f));
}

// ---------------- weight transpose fp32 [K][N] -> half [N][K] ----------------
__global__ void __launch_bounds__(256) transpose_h(const float* __restrict__ in,
                                                   __half* __restrict__ out,
                                                   int K, int N) {
    __shared__ float t[32][33];
    int n0 = blockIdx.x * 32, k0 = blockIdx.y * 32;
    int tx = threadIdx.x & 31, ty = threadIdx.x >> 5;   // 32 x 8
    #pragma unroll
    for (int j = 0; j < 4; j++)
        t[ty + j * 8][tx] = in[(size_t)(k0 + ty + j * 8) * N + n0 + tx];
    __syncthreads();
    #pragma unroll
    for (int j = 0; j < 4; j++)
        out[(size_t)(n0 + ty + j * 8) * K + k0 + tx] = __float2half_rn(t[tx][ty + j * 8]);
}

// ---------------- LayerNorm fp32 in -> half out -------------------------------
__global__ void __launch_bounds__(256) ln_kernel(const float* __restrict__ x,
                                                 const float* __restrict__ g,
                                                 const float* __restrict__ b,
                                                 __half* __restrict__ out) {
    int row = blockIdx.x;
    int tid = threadIdx.x;
    const float* xr = x + (size_t)row * Dq;
    float4 v = *(const float4*)&xr[tid * 4];
    float sum = v.x + v.y + v.z + v.w;
    float sq  = v.x*v.x + v.y*v.y + v.z*v.z + v.w*v.w;
    #pragma unroll
    for (int o = 16; o; o >>= 1) {
        sum += __shfl_xor_sync(0xffffffffu, sum, o);
        sq  += __shfl_xor_sync(0xffffffffu, sq,  o);
    }
    __shared__ float red0[8], red1[8];
    int wid = tid >> 5, lane = tid & 31;
    if (lane == 0) { red0[wid] = sum; red1[wid] = sq; }
    __syncthreads();
    float tot = 0.f, totq = 0.f;
    #pragma unroll
    for (int i = 0; i < 8; i++) { tot += red0[i]; totq += red1[i]; }
    float mu  = tot * (1.0f / Dq);
    float var = totq * (1.0f / Dq) - mu * mu;
    float inv = rsqrtf(var + 1e-5f);
    float4 gv = *(const float4*)&g[tid * 4];
    float4 bv = *(const float4*)&b[tid * 4];
    uint2 o2;
    o2.x = packh((v.x - mu) * inv * gv.x + bv.x, (v.y - mu) * inv * gv.y + bv.y);
    o2.y = packh((v.z - mu) * inv * gv.z + bv.z, (v.w - mu) * inv * gv.w + bv.w);
    *(uint2*)&out[(size_t)row * Dq + tid * 4] = o2;
}

// ---------------- RoPE in place on q and k parts of g_qkv -------------------
__global__ void __launch_bounds__(256) rope_kernel(const float* __restrict__ freqs) {
    int idx = blockIdx.x * blockDim.x + threadIdx.x;
    if (idx >= Lq * Hq * (HDq / 2)) return;
    int t = idx & 31;
    int h = (idx >> 5) & 15;
    int l = idx >> 9;
    float c = freqs[((size_t)l * 32 + t) * 2 + 0];
    float s = freqs[((size_t)l * 32 + t) * 2 + 1];
    #pragma unroll
    for (int part = 0; part < 2; part++) {
        float* p = &g_qkv[(size_t)l * (3 * Dq) + part * Dq + h * HDq + 2 * t];
        float a = p[0], bb = p[1];
        p[0] = a * c - bb * s;
        p[1] = a * s + bb * c;
    }
}

// ---------------- FP16 GEMM: 128x128 tile, BK=32, 4-stage cp.async ----------
// A half [M][K] row-major, BT half [N][K] row-major.
// D[m][n] = sum_k A[m][k]*BT[n][k] via mma.m16n8k16.row.col.
// smem halves: A stage s at s*5120 (128 rows x 40), B at 20480 + s*5120.
// EPI: 0 none (fp32 C), 1 bias+gelu (HALF C), 2 +res (fp32), 3 bias+res (fp32).
#define GEMM_SMEM_BYTES (40960 * 2)
template <int EPI>
__global__ void __launch_bounds__(256) hgemm(const __half* __restrict__ A,
                                             const __half* __restrict__ BT,
                                             const float* __restrict__ bias,
                                             const float* __restrict__ res,
                                             void* __restrict__ Cv,
                                             int N, int K) {
    extern __shared__ __half smh[];
    const int tid  = threadIdx.x;
    const int warp = tid >> 5, lane = tid & 31;
    const int gid  = lane >> 2, tig = lane & 3;
    const int wm   = warp >> 2, wn = warp & 3;
    const int m_w  = wm * 64,   n_w = wn * 32;
    const int bm   = blockIdx.y, bn = blockIdx.x;

    // cp.async mapping: thread owns row tid>>1 of A and of BT; chunks {c, c+2}
    const int row = tid >> 1;
    const int ch0 = (tid & 1) * 8;          // half-offset 0 or 8 (chunk 0/1)
    const __half* Ar = A  + (size_t)(bm * 128 + row) * K;
    const __half* Br = BT + (size_t)(bn * 128 + row) * K;

    uint32_t dA[4][2], dB[4][2];
    #pragma unroll
    for (int s = 0; s < 4; s++) {
        dA[s][0] = (uint32_t)__cvta_generic_to_shared(&smh[s*5120 + row*40 + ch0]);
        dA[s][1] = dA[s][0] + 16 * 2;       // +16 halves
        dB[s][0] = (uint32_t)__cvta_generic_to_shared(&smh[20480 + s*5120 + row*40 + ch0]);
        dB[s][1] = dB[s][0] + 16 * 2;
    }

    float acc[4][4][4];
    #pragma unroll
    for (int i = 0; i < 4; i++)
        #pragma unroll
        for (int j = 0; j < 4; j++)
            #pragma unroll
            for (int c = 0; c < 4; c++) acc[i][j][c] = 0.f;

    const int niter = K >> 5;
    #pragma unroll
    for (int s = 0; s < 3; s++) {
        int k0 = s * 32;
        cp16(dA[s][0], Ar + k0 + ch0);
        cp16(dA[s][1], Ar + k0 + ch0 + 16);
        cp16(dB[s][0], Br + k0 + ch0);
        cp16(dB[s][1], Br + k0 + ch0 + 16);
        CP_COMMIT();
    }

    for (int kt = 0; kt < niter; kt++) {
        CP_WAIT2();
        __syncthreads();
        const int s = kt & 3;
        if (kt + 3 < niter) {
            const int sn = (kt + 3) & 3;
            const int k0 = (kt + 3) << 5;
            cp16(dA[sn][0], Ar + k0 + ch0);
            cp16(dA[sn][1], Ar + k0 + ch0 + 16);
            cp16(dB[sn][0], Br + k0 + ch0);
            cp16(dB[sn][1], Br + k0 + ch0 + 16);
        }
        CP_COMMIT();

        const __half* As_ = smh + s * 5120;
        const __half* Bs_ = smh + 20480 + s * 5120;
        #pragma unroll
        for (int kk = 0; kk < 2; kk++) {
            const int kb = kk * 16 + 2 * tig;
            uint32_t afr[4][4];
            #pragma unroll
            for (int mt = 0; mt < 4; mt++) {
                int r0 = m_w + mt * 16 + gid;
                afr[mt][0] = *(const uint32_t*)&As_[r0 * 40 + kb];
                afr[mt][1] = *(const uint32_t*)&As_[(r0 + 8) * 40 + kb];
                afr[mt][2] = *(const uint32_t*)&As_[r0 * 40 + kb + 8];
                afr[mt][3] = *(const uint32_t*)&As_[(r0 + 8) * 40 + kb + 8];
            }
            uint32_t bfr[4][2];
            #pragma unroll
            for (int nt = 0; nt < 4; nt++) {
                int c0 = n_w + nt * 8 + gid;
                bfr[nt][0] = *(const uint32_t*)&Bs_[c0 * 40 + kb];
                bfr[nt][1] = *(const uint32_t*)&Bs_[c0 * 40 + kb + 8];
            }
            #pragma unroll
            for (int mt = 0; mt < 4; mt++)
                #pragma unroll
                for (int nt = 0; nt < 4; nt++)
                    mma_f16(acc[mt][nt], afr[mt], bfr[nt]);
        }
    }

    // epilogue
    #pragma unroll
    for (int mt = 0; mt < 4; mt++) {
        int row0 = bm * 128 + m_w + mt * 16 + gid;
        #pragma unroll
        for (int nt = 0; nt < 4; nt++) {
            int col = bn * 128 + n_w + nt * 8 + tig * 2;
            #pragma unroll
            for (int half_ = 0; half_ < 2; half_++) {
                int r = row0 + half_ * 8;
                float r0 = acc[mt][nt][half_ * 2 + 0];
                float r1 = acc[mt][nt][half_ * 2 + 1];
                if (EPI == 1 || EPI == 3) {
                    r0 += bias[col];
                    r1 += bias[col + 1];
                }
                size_t base = (size_t)r * N + col;
                if (EPI == 1) {
                    r0 = gelu_exact(r0); r1 = gelu_exact(r1);
                    *(uint32_t*)&((__half*)Cv)[base] = packh(r0, r1);
                } else {
                    if (EPI == 2 || EPI == 3) {
                        float2 rv = *(const float2*)&res[base];
                        r0 += rv.x; r1 += rv.y;
                    }
                    *(float2*)&((float*)Cv)[base] = make_float2(r0, r1);
                }
            }
        }
    }
}

// ---------------- Attention: fp16 tensor-core flash, 128 q-rows / block -----
// grid (8 qtiles, 16 heads, 4 segs), 256 threads (8 warps x 16 q-rows).
__global__ void __launch_bounds__(256) attn_kernel() {
    __shared__ __half Ks[64 * 72];
    __shared__ __half Vs[64 * 72];
    __shared__ __half Ps[128 * 72];

    const int qt = blockIdx.x, head = blockIdx.y, seg = blockIdx.z;
    const int tid = threadIdx.x, warp = tid >> 5, lane = tid & 31;
    const int gid = lane >> 2, tig = lane & 3;
    const int q0 = seg * 1024 + qt * 128;
    const int wrow = warp * 16;
    const float scale = 0.125f;

    // Q fragments: 4 k16 steps x 4 regs, resident
    uint32_t qf[4][4];
    {
        const float* Q0 = g_qkv + (size_t)(q0 + wrow + gid) * (3 * Dq) + head * HDq;
        const float* Q1 = Q0 + (size_t)8 * (3 * Dq);
        #pragma unroll
        for (int kk = 0; kk < 4; kk++) {
            int kb = kk * 16 + 2 * tig;
            qf[kk][0] = packh(Q0[kb] * scale,     Q0[kb + 1] * scale);
            qf[kk][1] = packh(Q1[kb] * scale,     Q1[kb + 1] * scale);
            qf[kk][2] = packh(Q0[kb + 8] * scale, Q0[kb + 9] * scale);
            qf[kk][3] = packh(Q1[kb + 8] * scale, Q1[kb + 9] * scale);
        }
    }

    float o[8][4];
    #pragma unroll
    for (int nt = 0; nt < 8; nt++)
        #pragma unroll
        for (int j = 0; j < 4; j++) o[nt][j] = 0.f;
    float m0 = -1e30f, m1 = -1e30f, l0 = 0.f, l1 = 0.f;

    for (int chn = 0; chn < 16; chn++) {
        __syncthreads();
        #pragma unroll
        for (int i = 0; i < 4; i++) {
            int lin = i * 256 + tid;
            int key = lin >> 4;
            int d4  = (lin & 15) * 4;
            const float* base = g_qkv + (size_t)(seg * 1024 + chn * 64 + key) * (3 * Dq)
                              + head * HDq + d4;
            float4 k4 = *(const float4*)(base + Dq);
            float4 v4 = *(const float4*)(base + 2 * Dq);
            uint2 kp, vp;
            kp.x = packh(k4.x, k4.y); kp.y = packh(k4.z, k4.w);
            vp.x = packh(v4.x, v4.y); vp.y = packh(v4.z, v4.w);
            *(uint2*)&Ks[key * 72 + d4] = kp;
            *(uint2*)&Vs[key * 72 + d4] = vp;
        }
        __syncthreads();

        // S = Q * K^T (16x64 per warp)
        float s[8][4];
        #pragma unroll
        for (int nt = 0; nt < 8; nt++)
            #pragma unroll
            for (int j = 0; j < 4; j++) s[nt][j] = 0.f;
        #pragma unroll
        for (int kk = 0; kk < 4; kk++) {
            const int kb = kk * 16 + 2 * tig;
            #pragma unroll
            for (int nt = 0; nt < 8; nt++) {
                const int c0 = (nt * 8 + gid) * 72;
                uint32_t bb[2];
                bb[0] = *(const uint32_t*)&Ks[c0 + kb];
                bb[1] = *(const uint32_t*)&Ks[c0 + kb + 8];
                mma_f16(s[nt], qf[kk], bb);
            }
        }

        // online softmax (rows gid and gid+8)
        float mc0 = -1e30f, mc1 = -1e30f;
        #pragma unroll
        for (int nt = 0; nt < 8; nt++) {
            mc0 = fmaxf(mc0, fmaxf(s[nt][0], s[nt][1]));
            mc1 = fmaxf(mc1, fmaxf(s[nt][2], s[nt][3]));
        }
        mc0 = fmaxf(mc0, __shfl_xor_sync(0xffffffffu, mc0, 1));
        mc0 = fmaxf(mc0, __shfl_xor_sync(0xffffffffu, mc0, 2));
        mc1 = fmaxf(mc1, __shfl_xor_sync(0xffffffffu, mc1, 1));
        mc1 = fmaxf(mc1, __shfl_xor_sync(0xffffffffu, mc1, 2));
        float mn0 = fmaxf(m0, mc0), mn1 = fmaxf(m1, mc1);
        float c0 = __expf(m0 - mn0), c1 = __expf(m1 - mn1);
        m0 = mn0; m1 = mn1;
        l0 *= c0;  l1 *= c1;
        #pragma unroll
        for (int nt = 0; nt < 8; nt++) {
            o[nt][0] *= c0; o[nt][1] *= c0;
            o[nt][2] *= c1; o[nt][3] *= c1;
        }
        #pragma unroll
        for (int nt = 0; nt < 8; nt++) {
            float p0 = __expf(s[nt][0] - mn0);
            float p1 = __expf(s[nt][1] - mn0);
            float p2 = __expf(s[nt][2] - mn1);
            float p3 = __expf(s[nt][3] - mn1);
            uint32_t u01 = packh(p0, p1);
            uint32_t u23 = packh(p2, p3);
            __half2 h01 = *(__half2*)&u01;
            __half2 h23 = *(__half2*)&u23;
            l0 += __half2float(h01.x) + __half2float(h01.y);
            l1 += __half2float(h23.x) + __half2float(h23.y);
            *(uint32_t*)&Ps[(wrow + gid) * 72 + nt * 8 + tig * 2]     = u01;
            *(uint32_t*)&Ps[(wrow + gid + 8) * 72 + nt * 8 + tig * 2] = u23;
        }
        __syncwarp();

        // O += P * V
        #pragma unroll
        for (int kk = 0; kk < 4; kk++) {
            const int kb = kk * 16 + 2 * tig;
            uint32_t af[4];
            af[0] = *(const uint32_t*)&Ps[(wrow + gid) * 72 + kb];
            af[1] = *(const uint32_t*)&Ps[(wrow + gid + 8) * 72 + kb];
            af[2] = *(const uint32_t*)&Ps[(wrow + gid) * 72 + kb + 8];
            af[3] = *(const uint32_t*)&Ps[(wrow + gid + 8) * 72 + kb + 8];
            #pragma unroll
            for (int nt = 0; nt < 8; nt++) {
                const int d = nt * 8 + gid;
                uint32_t bb[2];
                bb[0] = *(uint32_t*)&(__halves2half2(Vs[kb * 72 + d],
                                                     Vs[(kb + 1) * 72 + d]));
                bb[1] = *(uint32_t*)&(__halves2half2(Vs[(kb + 8) * 72 + d],
                                                     Vs[(kb + 9) * 72 + d]));
                mma_f16(o[nt], af, bb);
            }
        }
    }

    l0 += __shfl_xor_sync(0xffffffffu, l0, 1);
    l0 += __shfl_xor_sync(0xffffffffu, l0, 2);
    l1 += __shfl_xor_sync(0xffffffffu, l1, 1);
    l1 += __shfl_xor_sync(0xffffffffu, l1, 2);
    float inv0 = 1.0f / l0, inv1 = 1.0f / l1;

    __half* O0 = g_attnh + (size_t)(q0 + wrow + gid) * Dq + head * HDq;
    __half* O1 = O0 + (size_t)8 * Dq;
    #pragma unroll
    for (int nt = 0; nt < 8; nt++) {
        *(uint32_t*)&O0[nt * 8 + tig * 2] = packh(o[nt][0] * inv0, o[nt][1] * inv0);
        *(uint32_t*)&O1[nt * 8 + tig * 2] = packh(o[nt][2] * inv1, o[nt][3] * inv1);
    }
}

// ---------------- host orchestration ---------------------------------------
extern "C" void kernel_launch(void* const* d_in, const int* in_sizes, int n_in,
                              void* d_out, int out_size) {
    const float* hidden = (const float*)d_in[0];
    const float* rope   = (const float*)d_in[2];
    const float* ln0_g  = (const float*)d_in[3];
    const float* ln0_b  = (const float*)d_in[4];
    const float* ln1_g  = (const float*)d_in[5];
    const float* ln1_b  = (const float*)d_in[6];
    const float* w_qkv  = (const float*)d_in[7];
    const float* w_o    = (const float*)d_in[8];
    const float* w_fc0  = (const float*)d_in[9];
    const float* b_fc0  = (const float*)d_in[10];
    const float* w_fc1  = (const float*)d_in[11];
    const float* b_fc1  = (const float*)d_in[12];
    float* out = (float*)d_out;

    float  *p_qkv, *p_h;
    __half *p_xlnh, *p_ylnh, *p_attnh, *p_fc0h;
    __half *p_wqkvT, *p_woT, *p_fc0T, *p_fc1T;
    cudaGetSymbolAddress((void**)&p_qkv,   g_qkv);
    cudaGetSymbolAddress((void**)&p_h,     g_h);
    cudaGetSymbolAddress((void**)&p_xlnh,  g_xlnh);
    cudaGetSymbolAddress((void**)&p_ylnh,  g_ylnh);
    cudaGetSymbolAddress((void**)&p_attnh, g_attnh);
    cudaGetSymbolAddress((void**)&p_fc0h,  g_fc0h);
    cudaGetSymbolAddress((void**)&p_wqkvT, g_wqkvT);
    cudaGetSymbolAddress((void**)&p_woT,   g_woT);
    cudaGetSymbolAddress((void**)&p_fc0T,  g_fc0T);
    cudaGetSymbolAddress((void**)&p_fc1T,  g_fc1T);

    cudaFuncSetAttribute(hgemm<0>, cudaFuncAttributeMaxDynamicSharedMemorySize, GEMM_SMEM_BYTES);
    cudaFuncSetAttribute(hgemm<1>, cudaFuncAttributeMaxDynamicSharedMemorySize, GEMM_SMEM_BYTES);
    cudaFuncSetAttribute(hgemm<2>, cudaFuncAttributeMaxDynamicSharedMemorySize, GEMM_SMEM_BYTES);
    cudaFuncSetAttribute(hgemm<3>, cudaFuncAttributeMaxDynamicSharedMemorySize, GEMM_SMEM_BYTES);

    // 0. weight transposes -> half [N][K]
    transpose_h<<<dim3(3 * Dq / 32, Dq / 32), 256>>>(w_qkv, p_wqkvT, Dq, 3 * Dq);
    transpose_h<<<dim3(Dq / 32, Dq / 32), 256>>>(w_o,   p_woT,  Dq, Dq);
    transpose_h<<<dim3(Mq / 32, Dq / 32), 256>>>(w_fc0, p_fc0T, Dq, Mq);
    transpose_h<<<dim3(Dq / 32, Mq / 32), 256>>>(w_fc1, p_fc1T, Mq, Dq);

    // 1. LN0 -> half
    ln_kernel<<<Lq, 256>>>(hidden, ln0_g, ln0_b, p_xlnh);
    // 2. QKV = xln @ w_qkv -> fp32
    hgemm<0><<<dim3(3 * Dq / 128, Lq / 128), 256, GEMM_SMEM_BYTES>>>(
        p_xlnh, p_wqkvT, nullptr, nullptr, p_qkv, 3 * Dq, Dq);
    // 3. RoPE (fp32 in place)
    rope_kernel<<<(Lq * Hq * 32) / 256, 256>>>(rope);
    // 4. Attention -> half
    attn_kernel<<<dim3(8, Hq, 4), 256>>>();
    // 5. h = hidden + attn @ w_o -> fp32
    hgemm<2><<<dim3(Dq / 128, Lq / 128), 256, GEMM_SMEM_BYTES>>>(
        p_attnh, p_woT, nullptr, hidden, p_h, Dq, Dq);
    // 6. LN1 -> half
    ln_kernel<<<Lq, 256>>>(p_h, ln1_g, ln1_b, p_ylnh);
    // 7. fc0 + bias + gelu -> half
    hgemm<1><<<dim3(Mq / 128, Lq / 128), 256, GEMM_SMEM_BYTES>>>(
        p_ylnh, p_fc0T, b_fc0, nullptr, p_fc0h, Mq, Dq);
    // 8. out = h + fc0g @ w_fc1 + b_fc1 -> fp32
    hgemm<3><<<dim3(Dq / 128, Lq / 128), 256, GEMM_SMEM_BYTES>>>(
        p_fc0h, p_fc1T, b_fc1, p_h, out, Dq, Mq);
    (void)in_sizes; (void)n_in; (void)out_size;
}

// round 6
// speedup vs baseline: 6.0091x; 1.0561x over previous
#include <cuda_runtime.h>
#include <cuda_fp16.h>
#include <math.h>
#include <stdint.h>

#define Lq 4096
#define Dq 1024
#define Hq 16
#define HDq 64
#define Mq 4096

// ---------------- scratch (device globals; no allocation allowed) ----------
__device__ float  g_h    [Lq*Dq];            // fp32 residual+attn@w_o
__device__ __half g_qkvh [Lq*3*Dq];          // half qkv (rope fused in epilogue)
__device__ __half g_xlnh [Lq*Dq];
__device__ __half g_ylnh [Lq*Dq];
__device__ __half g_attnh[Lq*Dq];
__device__ __half g_fc0h [(size_t)Lq*Mq];
// half transposed weights [N][K]
__device__ __half g_wqkvT[3*Dq*Dq];
__device__ __half g_woT  [Dq*Dq];
__device__ __half g_fc0T [(size_t)Mq*Dq];
__device__ __half g_fc1T [(size_t)Dq*Mq];

// ---------------- helpers ----------------------------------------------------
__device__ __forceinline__ uint32_t smem_u32(const void* p) {
    uint32_t a;
    asm("{ .reg .u64 t; cvta.to.shared.u64 t, %1; cvt.u32.u64 %0, t; }" : "=r"(a) : "l"(p));
    return a;
}
__device__ __forceinline__ void cp16(uint32_t dst, const void* src) {
    asm volatile("cp.async.cg.shared.global [%0], [%1], 16;" :: "r"(dst), "l"(src));
}
#define CP_COMMIT() asm volatile("cp.async.commit_group;" ::: "memory")
#define CP_WAIT2()  asm volatile("cp.async.wait_group 2;" ::: "memory")

__device__ __forceinline__ uint32_t packh(float a, float b) {
    __half2 h = __floats2half2_rn(a, b);
    return *(uint32_t*)&h;
}
__device__ __forceinline__ void mma_f16(float* d, const uint32_t* a, const uint32_t* b) {
    asm volatile(
        "mma.sync.aligned.m16n8k16.row.col.f32.f16.f16.f32 "
        "{%0,%1,%2,%3}, {%4,%5,%6,%7}, {%8,%9}, {%0,%1,%2,%3};"
        : "+f"(d[0]), "+f"(d[1]), "+f"(d[2]), "+f"(d[3])
        : "r"(a[0]), "r"(a[1]), "r"(a[2]), "r"(a[3]), "r"(b[0]), "r"(b[1]));
}
__device__ __forceinline__ void ldsm_x2_t(uint32_t& r0, uint32_t& r1, uint32_t addr) {
    asm volatile("ldmatrix.sync.aligned.m8n8.x2.trans.shared.b16 {%0,%1}, [%2];"
                 : "=r"(r0), "=r"(r1) : "r"(addr));
}
__device__ __forceinline__ float gelu_exact(float x) {
    return 0.5f * x * (1.0f + erff(x * 0.70710678118654752f));
}

// ---------------- weight transpose fp32 [K][N] -> half [N][K] ----------------
__global__ void __launch_bounds__(256) transpose_h(const float* __restrict__ in,
                                                   __half* __restrict__ out,
                                                   int K, int N) {
    __shared__ float t[32][33];
    int n0 = blockIdx.x * 32, k0 = blockIdx.y * 32;
    int tx = threadIdx.x & 31, ty = threadIdx.x >> 5;   // 32 x 8
    #pragma unroll
    for (int j = 0; j < 4; j++)
        t[ty + j * 8][tx] = in[(size_t)(k0 + ty + j * 8) * N + n0 + tx];
    __syncthreads();
    #pragma unroll
    for (int j = 0; j < 4; j++)
        out[(size_t)(n0 + ty + j * 8) * K + k0 + tx] = __float2half_rn(t[tx][ty + j * 8]);
}

// ---------------- LayerNorm fp32 in -> half out -------------------------------
__global__ void __launch_bounds__(256) ln_kernel(const float* __restrict__ x,
                                                 const float* __restrict__ g,
                                                 const float* __restrict__ b,
                                                 __half* __restrict__ out) {
    int row = blockIdx.x;
    int tid = threadIdx.x;
    const float* xr = x + (size_t)row * Dq;
    float4 v = *(const float4*)&xr[tid * 4];
    float sum = v.x + v.y + v.z + v.w;
    float sq  = v.x*v.x + v.y*v.y + v.z*v.z + v.w*v.w;
    #pragma unroll
    for (int o = 16; o; o >>= 1) {
        sum += __shfl_xor_sync(0xffffffffu, sum, o);
        sq  += __shfl_xor_sync(0xffffffffu, sq,  o);
    }
    __shared__ float red0[8], red1[8];
    int wid = tid >> 5, lane = tid & 31;
    if (lane == 0) { red0[wid] = sum; red1[wid] = sq; }
    __syncthreads();
    float tot = 0.f, totq = 0.f;
    #pragma unroll
    for (int i = 0; i < 8; i++) { tot += red0[i]; totq += red1[i]; }
    float mu  = tot * (1.0f / Dq);
    float var = totq * (1.0f / Dq) - mu * mu;
    float inv = rsqrtf(var + 1e-5f);
    float4 gv = *(const float4*)&g[tid * 4];
    float4 bv = *(const float4*)&b[tid * 4];
    uint2 o2;
    o2.x = packh((v.x - mu) * inv * gv.x + bv.x, (v.y - mu) * inv * gv.y + bv.y);
    o2.y = packh((v.z - mu) * inv * gv.z + bv.z, (v.w - mu) * inv * gv.w + bv.w);
    *(uint2*)&out[(size_t)row * Dq + tid * 4] = o2;
}

// ---------------- FP16 GEMM: 128x128 tile, BK=32, 4-stage cp.async ----------
// EPI: 0 none (fp32 C), 1 bias+gelu (half C), 2 +res (fp32), 3 bias+res (fp32),
//      4 rope fused (half C, QKV layout).
#define GEMM_SMEM_BYTES (40960 * 2)
template <int EPI>
__global__ void __launch_bounds__(256) hgemm(const __half* __restrict__ A,
                                             const __half* __restrict__ BT,
                                             const float* __restrict__ bias,
                                             const float* __restrict__ res,
                                             void* __restrict__ Cv,
                                             int N, int K) {
    extern __shared__ __half smh[];
    const int tid  = threadIdx.x;
    const int warp = tid >> 5, lane = tid & 31;
    const int gid  = lane >> 2, tig = lane & 3;
    const int wm   = warp >> 2, wn = warp & 3;
    const int m_w  = wm * 64,   n_w = wn * 32;
    const int bm   = blockIdx.y, bn = blockIdx.x;

    const int row = tid >> 1;
    const int ch0 = (tid & 1) * 8;
    const __half* Ar = A  + (size_t)(bm * 128 + row) * K;
    const __half* Br = BT + (size_t)(bn * 128 + row) * K;

    uint32_t dA[4][2], dB[4][2];
    #pragma unroll
    for (int s = 0; s < 4; s++) {
        dA[s][0] = (uint32_t)__cvta_generic_to_shared(&smh[s*5120 + row*40 + ch0]);
        dA[s][1] = dA[s][0] + 16 * 2;
        dB[s][0] = (uint32_t)__cvta_generic_to_shared(&smh[20480 + s*5120 + row*40 + ch0]);
        dB[s][1] = dB[s][0] + 16 * 2;
    }

    float acc[4][4][4];
    #pragma unroll
    for (int i = 0; i < 4; i++)
        #pragma unroll
        for (int j = 0; j < 4; j++)
            #pragma unroll
            for (int c = 0; c < 4; c++) acc[i][j][c] = 0.f;

    const int niter = K >> 5;
    #pragma unroll
    for (int s = 0; s < 3; s++) {
        int k0 = s * 32;
        cp16(dA[s][0], Ar + k0 + ch0);
        cp16(dA[s][1], Ar + k0 + ch0 + 16);
        cp16(dB[s][0], Br + k0 + ch0);
        cp16(dB[s][1], Br + k0 + ch0 + 16);
        CP_COMMIT();
    }

    for (int kt = 0; kt < niter; kt++) {
        CP_WAIT2();
        __syncthreads();
        const int s = kt & 3;
        if (kt + 3 < niter) {
            const int sn = (kt + 3) & 3;
            const int k0 = (kt + 3) << 5;
            cp16(dA[sn][0], Ar + k0 + ch0);
            cp16(dA[sn][1], Ar + k0 + ch0 + 16);
            cp16(dB[sn][0], Br + k0 + ch0);
            cp16(dB[sn][1], Br + k0 + ch0 + 16);
        }
        CP_COMMIT();

        const __half* As_ = smh + s * 5120;
        const __half* Bs_ = smh + 20480 + s * 5120;
        #pragma unroll
        for (int kk = 0; kk < 2; kk++) {
            const int kb = kk * 16 + 2 * tig;
            uint32_t afr[4][4];
            #pragma unroll
            for (int mt = 0; mt < 4; mt++) {
                int r0 = m_w + mt * 16 + gid;
                afr[mt][0] = *(const uint32_t*)&As_[r0 * 40 + kb];
                afr[mt][1] = *(const uint32_t*)&As_[(r0 + 8) * 40 + kb];
                afr[mt][2] = *(const uint32_t*)&As_[r0 * 40 + kb + 8];
                afr[mt][3] = *(const uint32_t*)&As_[(r0 + 8) * 40 + kb + 8];
            }
            uint32_t bfr[4][2];
            #pragma unroll
            for (int nt = 0; nt < 4; nt++) {
                int c0 = n_w + nt * 8 + gid;
                bfr[nt][0] = *(const uint32_t*)&Bs_[c0 * 40 + kb];
                bfr[nt][1] = *(const uint32_t*)&Bs_[c0 * 40 + kb + 8];
            }
            #pragma unroll
            for (int mt = 0; mt < 4; mt++)
                #pragma unroll
                for (int nt = 0; nt < 4; nt++)
                    mma_f16(acc[mt][nt], afr[mt], bfr[nt]);
        }
    }

    // epilogue (res doubles as rope_freqs pointer for EPI==4)
    const bool do_rope = (EPI == 4) && (bn < 16);
    #pragma unroll
    for (int mt = 0; mt < 4; mt++) {
        int row0 = bm * 128 + m_w + mt * 16 + gid;
        #pragma unroll
        for (int nt = 0; nt < 4; nt++) {
            int col = bn * 128 + n_w + nt * 8 + tig * 2;
            #pragma unroll
            for (int half_ = 0; half_ < 2; half_++) {
                int r = row0 + half_ * 8;
                float r0 = acc[mt][nt][half_ * 2 + 0];
                float r1 = acc[mt][nt][half_ * 2 + 1];
                if (EPI == 1 || EPI == 3) {
                    r0 += bias[col];
                    r1 += bias[col + 1];
                }
                size_t base = (size_t)r * N + col;
                if (EPI == 1) {
                    r0 = gelu_exact(r0); r1 = gelu_exact(r1);
                    *(uint32_t*)&((__half*)Cv)[base] = packh(r0, r1);
                } else if (EPI == 4) {
                    if (do_rope) {
                        int t = (col & 63) >> 1;
                        float2 cs = *(const float2*)&res[((size_t)r * 32 + t) * 2];
                        float a = r0, bb2 = r1;
                        r0 = a * cs.x - bb2 * cs.y;
                        r1 = a * cs.y + bb2 * cs.x;
                    }
                    *(uint32_t*)&((__half*)Cv)[base] = packh(r0, r1);
                } else {
                    if (EPI == 2 || EPI == 3) {
                        float2 rv = *(const float2*)&res[base];
                        r0 += rv.x; r1 += rv.y;
                    }
                    *(float2*)&((float*)Cv)[base] = make_float2(r0, r1);
                }
            }
        }
    }
}

// ---------------- Attention: fp16 flash, register P, ldmatrix V --------------
// grid (8 qtiles, 16 heads, 4 segs), 256 threads (8 warps x 16 q-rows).
__global__ void __launch_bounds__(256) attn_kernel() {
    __shared__ __half Ks[64 * 72];
    __shared__ __half Vs[64 * 72];

    const int qt = blockIdx.x, head = blockIdx.y, seg = blockIdx.z;
    const int tid = threadIdx.x, warp = tid >> 5, lane = tid & 31;
    const int gid = lane >> 2, tig = lane & 3;
    const int q0 = seg * 1024 + qt * 128;
    const int wrow = warp * 16;
    const float scale = 0.125f;

    // Q fragments: raw 32-bit loads (scale applied to S post-MMA)
    uint32_t qf[4][4];
    {
        const __half* Q0 = g_qkvh + (size_t)(q0 + wrow + gid) * (3 * Dq) + head * HDq;
        const __half* Q1 = Q0 + (size_t)8 * (3 * Dq);
        #pragma unroll
        for (int kk = 0; kk < 4; kk++) {
            int kb = kk * 16 + 2 * tig;
            qf[kk][0] = *(const uint32_t*)&Q0[kb];
            qf[kk][1] = *(const uint32_t*)&Q1[kb];
            qf[kk][2] = *(const uint32_t*)&Q0[kb + 8];
            qf[kk][3] = *(const uint32_t*)&Q1[kb + 8];
        }
    }
    const uint32_t vrow = smem_u32(&Vs[(lane & 15) * 72]);

    float o[8][4];
    #pragma unroll
    for (int nt = 0; nt < 8; nt++)
        #pragma unroll
        for (int j = 0; j < 4; j++) o[nt][j] = 0.f;
    float m0 = -1e30f, m1 = -1e30f, l0 = 0.f, l1 = 0.f;

    for (int chn = 0; chn < 16; chn++) {
        __syncthreads();
        #pragma unroll
        for (int i = 0; i < 2; i++) {
            int slot = i * 256 + tid;            // 512 slots: 64 keys x 8 groups
            int key = slot >> 3, d8 = (slot & 7) * 8;
            const __half* base = g_qkvh + (size_t)(seg * 1024 + chn * 64 + key) * (3 * Dq)
                               + head * HDq + d8;
            *(uint4*)&Ks[key * 72 + d8] = *(const uint4*)(base + Dq);
            *(uint4*)&Vs[key * 72 + d8] = *(const uint4*)(base + 2 * Dq);
        }
        __syncthreads();

        // S = Q * K^T (16x64 per warp)
        float s[8][4];
        #pragma unroll
        for (int nt = 0; nt < 8; nt++)
            #pragma unroll
            for (int j = 0; j < 4; j++) s[nt][j] = 0.f;
        #pragma unroll
        for (int kk = 0; kk < 4; kk++) {
            const int kb = kk * 16 + 2 * tig;
            #pragma unroll
            for (int nt = 0; nt < 8; nt++) {
                const int c0 = (nt * 8 + gid) * 72;
                uint32_t bb[2];
                bb[0] = *(const uint32_t*)&Ks[c0 + kb];
                bb[1] = *(const uint32_t*)&Ks[c0 + kb + 8];
                mma_f16(s[nt], qf[kk], bb);
            }
        }
        #pragma unroll
        for (int nt = 0; nt < 8; nt++) {
            s[nt][0] *= scale; s[nt][1] *= scale;
            s[nt][2] *= scale; s[nt][3] *= scale;
        }

        // online softmax (rows gid and gid+8)
        float mc0 = -1e30f, mc1 = -1e30f;
        #pragma unroll
        for (int nt = 0; nt < 8; nt++) {
            mc0 = fmaxf(mc0, fmaxf(s[nt][0], s[nt][1]));
            mc1 = fmaxf(mc1, fmaxf(s[nt][2], s[nt][3]));
        }
        mc0 = fmaxf(mc0, __shfl_xor_sync(0xffffffffu, mc0, 1));
        mc0 = fmaxf(mc0, __shfl_xor_sync(0xffffffffu, mc0, 2));
        mc1 = fmaxf(mc1, __shfl_xor_sync(0xffffffffu, mc1, 1));
        mc1 = fmaxf(mc1, __shfl_xor_sync(0xffffffffu, mc1, 2));
        float mn0 = fmaxf(m0, mc0), mn1 = fmaxf(m1, mc1);
        float c0 = __expf(m0 - mn0), c1 = __expf(m1 - mn1);
        m0 = mn0; m1 = mn1;
        l0 *= c0;  l1 *= c1;
        #pragma unroll
        for (int nt = 0; nt < 8; nt++) {
            o[nt][0] *= c0; o[nt][1] *= c0;
            o[nt][2] *= c1; o[nt][3] *= c1;
        }

        // P: C-frag -> A-frag pure register pack
        uint32_t uf[8][2];
        #pragma unroll
        for (int nt = 0; nt < 8; nt++) {
            float p0 = __expf(s[nt][0] - mn0);
            float p1 = __expf(s[nt][1] - mn0);
            float p2 = __expf(s[nt][2] - mn1);
            float p3 = __expf(s[nt][3] - mn1);
            uf[nt][0] = packh(p0, p1);
            uf[nt][1] = packh(p2, p3);
            __half2 h01 = *(__half2*)&uf[nt][0];
            __half2 h23 = *(__half2*)&uf[nt][1];
            l0 += __half2float(h01.x) + __half2float(h01.y);
            l1 += __half2float(h23.x) + __half2float(h23.y);
        }

        // O += P * V  (V B-frags via ldmatrix.trans)
        #pragma unroll
        for (int kk = 0; kk < 4; kk++) {
            uint32_t af[4] = { uf[2*kk][0], uf[2*kk][1], uf[2*kk+1][0], uf[2*kk+1][1] };
            const uint32_t kbase = vrow + kk * 16 * 144;   // 16 rows x 144B
            #pragma unroll
            for (int nt = 0; nt < 8; nt++) {
                uint32_t bb[2];
                ldsm_x2_t(bb[0], bb[1], kbase + nt * 16);
                mma_f16(o[nt], af, bb);
            }
        }
    }

    l0 += __shfl_xor_sync(0xffffffffu, l0, 1);
    l0 += __shfl_xor_sync(0xffffffffu, l0, 2);
    l1 += __shfl_xor_sync(0xffffffffu, l1, 1);
    l1 += __shfl_xor_sync(0xffffffffu, l1, 2);
    float inv0 = 1.0f / l0, inv1 = 1.0f / l1;

    __half* O0 = g_attnh + (size_t)(q0 + wrow + gid) * Dq + head * HDq;
    __half* O1 = O0 + (size_t)8 * Dq;
    #pragma unroll
    for (int nt = 0; nt < 8; nt++) {
        *(uint32_t*)&O0[nt * 8 + tig * 2] = packh(o[nt][0] * inv0, o[nt][1] * inv0);
        *(uint32_t*)&O1[nt * 8 + tig * 2] = packh(o[nt][2] * inv1, o[nt][3] * inv1);
    }
}

// ---------------- host orchestration ---------------------------------------
extern "C" void kernel_launch(void* const* d_in, const int* in_sizes, int n_in,
                              void* d_out, int out_size) {
    const float* hidden = (const float*)d_in[0];
    const float* rope   = (const float*)d_in[2];
    const float* ln0_g  = (const float*)d_in[3];
    const float* ln0_b  = (const float*)d_in[4];
    const float* ln1_g  = (const float*)d_in[5];
    const float* ln1_b  = (const float*)d_in[6];
    const float* w_qkv  = (const float*)d_in[7];
    const float* w_o    = (const float*)d_in[8];
    const float* w_fc0  = (const float*)d_in[9];
    const float* b_fc0  = (const float*)d_in[10];
    const float* w_fc1  = (const float*)d_in[11];
    const float* b_fc1  = (const float*)d_in[12];
    float* out = (float*)d_out;

    float  *p_h;
    __half *p_qkvh, *p_xlnh, *p_ylnh, *p_attnh, *p_fc0h;
    __half *p_wqkvT, *p_woT, *p_fc0T, *p_fc1T;
    cudaGetSymbolAddress((void**)&p_h,     g_h);
    cudaGetSymbolAddress((void**)&p_qkvh,  g_qkvh);
    cudaGetSymbolAddress((void**)&p_xlnh,  g_xlnh);
    cudaGetSymbolAddress((void**)&p_ylnh,  g_ylnh);
    cudaGetSymbolAddress((void**)&p_attnh, g_attnh);
    cudaGetSymbolAddress((void**)&p_fc0h,  g_fc0h);
    cudaGetSymbolAddress((void**)&p_wqkvT, g_wqkvT);
    cudaGetSymbolAddress((void**)&p_woT,   g_woT);
    cudaGetSymbolAddress((void**)&p_fc0T,  g_fc0T);
    cudaGetSymbolAddress((void**)&p_fc1T,  g_fc1T);

    cudaFuncSetAttribute(hgemm<1>, cudaFuncAttributeMaxDynamicSharedMemorySize, GEMM_SMEM_BYTES);
    cudaFuncSetAttribute(hgemm<2>, cudaFuncAttributeMaxDynamicSharedMemorySize, GEMM_SMEM_BYTES);
    cudaFuncSetAttribute(hgemm<3>, cudaFuncAttributeMaxDynamicSharedMemorySize, GEMM_SMEM_BYTES);
    cudaFuncSetAttribute(hgemm<4>, cudaFuncAttributeMaxDynamicSharedMemorySize, GEMM_SMEM_BYTES);

    // 0. weight transposes -> half [N][K]
    transpose_h<<<dim3(3 * Dq / 32, Dq / 32), 256>>>(w_qkv, p_wqkvT, Dq, 3 * Dq);
    transpose_h<<<dim3(Dq / 32, Dq / 32), 256>>>(w_o,   p_woT,  Dq, Dq);
    transpose_h<<<dim3(Mq / 32, Dq / 32), 256>>>(w_fc0, p_fc0T, Dq, Mq);
    transpose_h<<<dim3(Dq / 32, Mq / 32), 256>>>(w_fc1, p_fc1T, Mq, Dq);

    // 1. LN0 -> half
    ln_kernel<<<Lq, 256>>>(hidden, ln0_g, ln0_b, p_xlnh);
    // 2. QKV = xln @ w_qkv, rope fused -> half
    hgemm<4><<<dim3(3 * Dq / 128, Lq / 128), 256, GEMM_SMEM_BYTES>>>(
        p_xlnh, p_wqkvT, nullptr, rope, p_qkvh, 3 * Dq, Dq);
    // 3. Attention -> half
    attn_kernel<<<dim3(8, Hq, 4), 256>>>();
    // 4. h = hidden + attn @ w_o -> fp32
    hgemm<2><<<dim3(Dq / 128, Lq / 128), 256, GEMM_SMEM_BYTES>>>(
        p_attnh, p_woT, nullptr, hidden, p_h, Dq, Dq);
    // 5. LN1 -> half
    ln_kernel<<<Lq, 256>>>(p_h, ln1_g, ln1_b, p_ylnh);
    // 6. fc0 + bias + gelu -> half
    hgemm<1><<<dim3(Mq / 128, Lq / 128), 256, GEMM_SMEM_BYTES>>>(
        p_ylnh, p_fc0T, b_fc0, nullptr, p_fc0h, Mq, Dq);
    // 7. out = h + fc0g @ w_fc1 + b_fc1 -> fp32
    hgemm<3><<<dim3(Dq / 128, Lq / 128), 256, GEMM_SMEM_BYTES>>>(
        p_fc0h, p_fc1T, b_fc1, p_h, out, Dq, Mq);
    (void)in_sizes; (void)n_in; (void)out_size;
}

// round 7
// speedup vs baseline: 6.5764x; 1.0944x over previous
#include <cuda_runtime.h>
#include <cuda_fp16.h>
#include <math.h>
#include <stdint.h>

#define Lq 4096
#define Dq 1024
#define Hq 16
#define HDq 64
#define Mq 4096

// ---------------- scratch (device globals; no allocation allowed) ----------
__device__ float  g_h    [Lq*Dq];            // fp32 residual+attn@w_o
__device__ __half g_qkvh [Lq*3*Dq];          // half qkv (rope fused in epilogue)
__device__ __half g_xlnh [Lq*Dq];
__device__ __half g_ylnh [Lq*Dq];
__device__ __half g_attnh[Lq*Dq];
__device__ __half g_fc0h [(size_t)Lq*Mq];
// half weights, original [K][N] layout (convert only, no transpose)
__device__ __half g_wqkvc[Dq*3*Dq];
__device__ __half g_woc  [Dq*Dq];
__device__ __half g_fc0c [(size_t)Dq*Mq];
__device__ __half g_fc1c [(size_t)Mq*Dq];

// ---------------- helpers ----------------------------------------------------
__device__ __forceinline__ uint32_t smem_u32(const void* p) {
    uint32_t a;
    asm("{ .reg .u64 t; cvta.to.shared.u64 t, %1; cvt.u32.u64 %0, t; }" : "=r"(a) : "l"(p));
    return a;
}
__device__ __forceinline__ void cp16(uint32_t dst, const void* src) {
    asm volatile("cp.async.cg.shared.global [%0], [%1], 16;" :: "r"(dst), "l"(src));
}
#define CP_COMMIT() asm volatile("cp.async.commit_group;" ::: "memory")
#define CP_WAIT2()  asm volatile("cp.async.wait_group 2;" ::: "memory")

__device__ __forceinline__ uint32_t packh(float a, float b) {
    __half2 h = __floats2half2_rn(a, b);
    return *(uint32_t*)&h;
}
__device__ __forceinline__ void mma_f16(float* d, const uint32_t* a, const uint32_t* b) {
    asm volatile(
        "mma.sync.aligned.m16n8k16.row.col.f32.f16.f16.f32 "
        "{%0,%1,%2,%3}, {%4,%5,%6,%7}, {%8,%9}, {%0,%1,%2,%3};"
        : "+f"(d[0]), "+f"(d[1]), "+f"(d[2]), "+f"(d[3])
        : "r"(a[0]), "r"(a[1]), "r"(a[2]), "r"(a[3]), "r"(b[0]), "r"(b[1]));
}
__device__ __forceinline__ void ldsm_x4(uint32_t* r, uint32_t addr) {
    asm volatile("ldmatrix.sync.aligned.m8n8.x4.shared.b16 {%0,%1,%2,%3}, [%4];"
                 : "=r"(r[0]), "=r"(r[1]), "=r"(r[2]), "=r"(r[3]) : "r"(addr));
}
__device__ __forceinline__ void ldsm_x2_t(uint32_t& r0, uint32_t& r1, uint32_t addr) {
    asm volatile("ldmatrix.sync.aligned.m8n8.x2.trans.shared.b16 {%0,%1}, [%2];"
                 : "=r"(r0), "=r"(r1) : "r"(addr));
}
__device__ __forceinline__ float gelu_exact(float x) {
    return 0.5f * x * (1.0f + erff(x * 0.70710678118654752f));
}

// ---------------- streaming fp32 -> half convert -----------------------------
__global__ void __launch_bounds__(256) cvt_h(const float* __restrict__ in,
                                             __half* __restrict__ out) {
    size_t i = ((size_t)blockIdx.x * 256 + threadIdx.x) * 8;
    float4 a = *(const float4*)&in[i];
    float4 b = *(const float4*)&in[i + 4];
    uint4 o;
    o.x = packh(a.x, a.y); o.y = packh(a.z, a.w);
    o.z = packh(b.x, b.y); o.w = packh(b.z, b.w);
    *(uint4*)&out[i] = o;
}

// ---------------- LayerNorm fp32 in -> half out -------------------------------
__global__ void __launch_bounds__(256) ln_kernel(const float* __restrict__ x,
                                                 const float* __restrict__ g,
                                                 const float* __restrict__ b,
                                                 __half* __restrict__ out) {
    int row = blockIdx.x;
    int tid = threadIdx.x;
    const float* xr = x + (size_t)row * Dq;
    float4 v = *(const float4*)&xr[tid * 4];
    float sum = v.x + v.y + v.z + v.w;
    float sq  = v.x*v.x + v.y*v.y + v.z*v.z + v.w*v.w;
    #pragma unroll
    for (int o = 16; o; o >>= 1) {
        sum += __shfl_xor_sync(0xffffffffu, sum, o);
        sq  += __shfl_xor_sync(0xffffffffu, sq,  o);
    }
    __shared__ float red0[8], red1[8];
    int wid = tid >> 5, lane = tid & 31;
    if (lane == 0) { red0[wid] = sum; red1[wid] = sq; }
    __syncthreads();
    float tot = 0.f, totq = 0.f;
    #pragma unroll
    for (int i = 0; i < 8; i++) { tot += red0[i]; totq += red1[i]; }
    float mu  = tot * (1.0f / Dq);
    float var = totq * (1.0f / Dq) - mu * mu;
    float inv = rsqrtf(var + 1e-5f);
    float4 gv = *(const float4*)&g[tid * 4];
    float4 bv = *(const float4*)&b[tid * 4];
    uint2 o2;
    o2.x = packh((v.x - mu) * inv * gv.x + bv.x, (v.y - mu) * inv * gv.y + bv.y);
    o2.y = packh((v.z - mu) * inv * gv.z + bv.z, (v.w - mu) * inv * gv.w + bv.w);
    *(uint2*)&out[(size_t)row * Dq + tid * 4] = o2;
}

// ---------------- FP16 GEMM: 128x128 tile, BK=32, 4-stage, ldmatrix ---------
// A half [M][K] row-major; B half [K][N] row-major (original layout).
// A-frags via ldmatrix.x4, B-frags via ldmatrix.x2.trans.
// smem bytes: A stage s at s*10240 (128 rows x 40 halves);
//             B stage s at 40960 + s*8704 (32 rows x 136 halves).
// EPI: 0 none (fp32 C), 1 bias+gelu (half C), 2 +res (fp32), 3 bias+res (fp32),
//      4 rope fused (half C, QKV layout).
#define GEMM_SMEM_BYTES (40960 + 4*8704)
template <int EPI>
__global__ void __launch_bounds__(256) hgemm(const __half* __restrict__ A,
                                             const __half* __restrict__ B,
                                             const float* __restrict__ bias,
                                             const float* __restrict__ res,
                                             void* __restrict__ Cv,
                                             int N, int K) {
    extern __shared__ char smc[];
    const uint32_t sbase = smem_u32(smc);
    const int tid  = threadIdx.x;
    const int warp = tid >> 5, lane = tid & 31;
    const int gid  = lane >> 2, tig = lane & 3;
    const int wm   = warp >> 2, wn = warp & 3;
    const int m_w  = wm * 64,   n_w = wn * 32;
    const int bm   = blockIdx.y, bn = blockIdx.x;

    // ---- cp.async mappings ----
    // A: thread -> row tid>>1, halves [ch0,ch0+8) and [ch0+16,ch0+24)
    const int arow = tid >> 1;
    const int ch0  = (tid & 1) * 8;
    const __half* Ar = A + (size_t)(bm * 128 + arow) * K;
    // B: thread -> k-row tid>>3, halves [(tid&7)*16, +8) and +8
    const int brow = tid >> 3;
    const int bc0  = (tid & 7) * 16;
    const __half* Br = B + (size_t)brow * N + bn * 128 + bc0;

    uint32_t dA[4][2], dB[4][2];
    #pragma unroll
    for (int s = 0; s < 4; s++) {
        dA[s][0] = sbase + s * 10240 + (arow * 40 + ch0) * 2;
        dA[s][1] = dA[s][0] + 32;
        dB[s][0] = sbase + 40960 + s * 8704 + (brow * 136 + bc0) * 2;
        dB[s][1] = dB[s][0] + 16;
    }

    // ---- ldmatrix per-lane base addresses ----
    const uint32_t a_base = sbase
        + ((m_w + ((lane >> 3) & 1) * 8 + (lane & 7)) * 40 + (lane >> 4) * 8) * 2;
    const uint32_t b_base = sbase + 40960 + ((lane & 15) * 136 + n_w) * 2;

    float acc[4][4][4];
    #pragma unroll
    for (int i = 0; i < 4; i++)
        #pragma unroll
        for (int j = 0; j < 4; j++)
            #pragma unroll
            for (int c = 0; c < 4; c++) acc[i][j][c] = 0.f;

    const int niter = K >> 5;
    #pragma unroll
    for (int s = 0; s < 3; s++) {
        int k0 = s * 32;
        cp16(dA[s][0], Ar + k0 + ch0);
        cp16(dA[s][1], Ar + k0 + ch0 + 16);
        cp16(dB[s][0], Br + (size_t)k0 * N);
        cp16(dB[s][1], Br + (size_t)k0 * N + 8);
        CP_COMMIT();
    }

    for (int kt = 0; kt < niter; kt++) {
        CP_WAIT2();
        __syncthreads();
        const int s = kt & 3;
        if (kt + 3 < niter) {
            const int sn = (kt + 3) & 3;
            const int k0 = (kt + 3) << 5;
            cp16(dA[sn][0], Ar + k0 + ch0);
            cp16(dA[sn][1], Ar + k0 + ch0 + 16);
            cp16(dB[sn][0], Br + (size_t)k0 * N);
            cp16(dB[sn][1], Br + (size_t)k0 * N + 8);
        }
        CP_COMMIT();

        const uint32_t aS = a_base + s * 10240;
        const uint32_t bS = b_base + s * 8704;
        #pragma unroll
        for (int kk = 0; kk < 2; kk++) {
            uint32_t afr[4][4];
            const uint32_t aK = aS + kk * 32;          // +16 halves
            #pragma unroll
            for (int mt = 0; mt < 4; mt++)
                ldsm_x4(afr[mt], aK + mt * 16 * 80);   // 16 rows x 80 B
            uint32_t bfr[4][2];
            const uint32_t bK = bS + kk * 16 * 272;    // 16 k-rows x 272 B
            #pragma unroll
            for (int nt = 0; nt < 4; nt++)
                ldsm_x2_t(bfr[nt][0], bfr[nt][1], bK + nt * 16);
            #pragma unroll
            for (int mt = 0; mt < 4; mt++)
                #pragma unroll
                for (int nt = 0; nt < 4; nt++)
                    mma_f16(acc[mt][nt], afr[mt], bfr[nt]);
        }
    }

    // epilogue (res doubles as rope_freqs pointer for EPI==4)
    const bool do_rope = (EPI == 4) && (bn < 16);
    #pragma unroll
    for (int mt = 0; mt < 4; mt++) {
        int row0 = bm * 128 + m_w + mt * 16 + gid;
        #pragma unroll
        for (int nt = 0; nt < 4; nt++) {
            int col = bn * 128 + n_w + nt * 8 + tig * 2;
            #pragma unroll
            for (int half_ = 0; half_ < 2; half_++) {
                int r = row0 + half_ * 8;
                float r0 = acc[mt][nt][half_ * 2 + 0];
                float r1 = acc[mt][nt][half_ * 2 + 1];
                if (EPI == 1 || EPI == 3) {
                    r0 += bias[col];
                    r1 += bias[col + 1];
                }
                size_t base = (size_t)r * N + col;
                if (EPI == 1) {
                    r0 = gelu_exact(r0); r1 = gelu_exact(r1);
                    *(uint32_t*)&((__half*)Cv)[base] = packh(r0, r1);
                } else if (EPI == 4) {
                    if (do_rope) {
                        int t = (col & 63) >> 1;
                        float2 cs = *(const float2*)&res[((size_t)r * 32 + t) * 2];
                        float a = r0, bb2 = r1;
                        r0 = a * cs.x - bb2 * cs.y;
                        r1 = a * cs.y + bb2 * cs.x;
                    }
                    *(uint32_t*)&((__half*)Cv)[base] = packh(r0, r1);
                } else {
                    if (EPI == 2 || EPI == 3) {
                        float2 rv = *(const float2*)&res[base];
                        r0 += rv.x; r1 += rv.y;
                    }
                    *(float2*)&((float*)Cv)[base] = make_float2(r0, r1);
                }
            }
        }
    }
}

// ---------------- Attention: fp16 flash, register P, ldmatrix V --------------
__global__ void __launch_bounds__(256) attn_kernel() {
    __shared__ __half Ks[64 * 72];
    __shared__ __half Vs[64 * 72];

    const int qt = blockIdx.x, head = blockIdx.y, seg = blockIdx.z;
    const int tid = threadIdx.x, warp = tid >> 5, lane = tid & 31;
    const int gid = lane >> 2, tig = lane & 3;
    const int q0 = seg * 1024 + qt * 128;
    const int wrow = warp * 16;
    const float scale = 0.125f;

    uint32_t qf[4][4];
    {
        const __half* Q0 = g_qkvh + (size_t)(q0 + wrow + gid) * (3 * Dq) + head * HDq;
        const __half* Q1 = Q0 + (size_t)8 * (3 * Dq);
        #pragma unroll
        for (int kk = 0; kk < 4; kk++) {
            int kb = kk * 16 + 2 * tig;
            qf[kk][0] = *(const uint32_t*)&Q0[kb];
            qf[kk][1] = *(const uint32_t*)&Q1[kb];
            qf[kk][2] = *(const uint32_t*)&Q0[kb + 8];
            qf[kk][3] = *(const uint32_t*)&Q1[kb + 8];
        }
    }
    const uint32_t vrow = smem_u32(&Vs[(lane & 15) * 72]);

    float o[8][4];
    #pragma unroll
    for (int nt = 0; nt < 8; nt++)
        #pragma unroll
        for (int j = 0; j < 4; j++) o[nt][j] = 0.f;
    float m0 = -1e30f, m1 = -1e30f, l0 = 0.f, l1 = 0.f;

    for (int chn = 0; chn < 16; chn++) {
        __syncthreads();
        #pragma unroll
        for (int i = 0; i < 2; i++) {
            int slot = i * 256 + tid;
            int key = slot >> 3, d8 = (slot & 7) * 8;
            const __half* base = g_qkvh + (size_t)(seg * 1024 + chn * 64 + key) * (3 * Dq)
                               + head * HDq + d8;
            *(uint4*)&Ks[key * 72 + d8] = *(const uint4*)(base + Dq);
            *(uint4*)&Vs[key * 72 + d8] = *(const uint4*)(base + 2 * Dq);
        }
        __syncthreads();

        float s[8][4];
        #pragma unroll
        for (int nt = 0; nt < 8; nt++)
            #pragma unroll
            for (int j = 0; j < 4; j++) s[nt][j] = 0.f;
        #pragma unroll
        for (int kk = 0; kk < 4; kk++) {
            const int kb = kk * 16 + 2 * tig;
            #pragma unroll
            for (int nt = 0; nt < 8; nt++) {
                const int c0 = (nt * 8 + gid) * 72;
                uint32_t bb[2];
                bb[0] = *(const uint32_t*)&Ks[c0 + kb];
                bb[1] = *(const uint32_t*)&Ks[c0 + kb + 8];
                mma_f16(s[nt], qf[kk], bb);
            }
        }
        #pragma unroll
        for (int nt = 0; nt < 8; nt++) {
            s[nt][0] *= scale; s[nt][1] *= scale;
            s[nt][2] *= scale; s[nt][3] *= scale;
        }

        float mc0 = -1e30f, mc1 = -1e30f;
        #pragma unroll
        for (int nt = 0; nt < 8; nt++) {
            mc0 = fmaxf(mc0, fmaxf(s[nt][0], s[nt][1]));
            mc1 = fmaxf(mc1, fmaxf(s[nt][2], s[nt][3]));
        }
        mc0 = fmaxf(mc0, __shfl_xor_sync(0xffffffffu, mc0, 1));
        mc0 = fmaxf(mc0, __shfl_xor_sync(0xffffffffu, mc0, 2));
        mc1 = fmaxf(mc1, __shfl_xor_sync(0xffffffffu, mc1, 1));
        mc1 = fmaxf(mc1, __shfl_xor_sync(0xffffffffu, mc1, 2));
        float mn0 = fmaxf(m0, mc0), mn1 = fmaxf(m1, mc1);
        float c0 = __expf(m0 - mn0), c1 = __expf(m1 - mn1);
        m0 = mn0; m1 = mn1;
        l0 *= c0;  l1 *= c1;
        #pragma unroll
        for (int nt = 0; nt < 8; nt++) {
            o[nt][0] *= c0; o[nt][1] *= c0;
            o[nt][2] *= c1; o[nt][3] *= c1;
        }

        uint32_t uf[8][2];
        #pragma unroll
        for (int nt = 0; nt < 8; nt++) {
            float p0 = __expf(s[nt][0] - mn0);
            float p1 = __expf(s[nt][1] - mn0);
            float p2 = __expf(s[nt][2] - mn1);
            float p3 = __expf(s[nt][3] - mn1);
            uf[nt][0] = packh(p0, p1);
            uf[nt][1] = packh(p2, p3);
            __half2 h01 = *(__half2*)&uf[nt][0];
            __half2 h23 = *(__half2*)&uf[nt][1];
            l0 += __half2float(h01.x) + __half2float(h01.y);
            l1 += __half2float(h23.x) + __half2float(h23.y);
        }

        #pragma unroll
        for (int kk = 0; kk < 4; kk++) {
            uint32_t af[4] = { uf[2*kk][0], uf[2*kk][1], uf[2*kk+1][0], uf[2*kk+1][1] };
            const uint32_t kbase = vrow + kk * 16 * 144;
            #pragma unroll
            for (int nt = 0; nt < 8; nt++) {
                uint32_t bb[2];
                ldsm_x2_t(bb[0], bb[1], kbase + nt * 16);
                mma_f16(o[nt], af, bb);
            }
        }
    }

    l0 += __shfl_xor_sync(0xffffffffu, l0, 1);
    l0 += __shfl_xor_sync(0xffffffffu, l0, 2);
    l1 += __shfl_xor_sync(0xffffffffu, l1, 1);
    l1 += __shfl_xor_sync(0xffffffffu, l1, 2);
    float inv0 = 1.0f / l0, inv1 = 1.0f / l1;

    __half* O0 = g_attnh + (size_t)(q0 + wrow + gid) * Dq + head * HDq;
    __half* O1 = O0 + (size_t)8 * Dq;
    #pragma unroll
    for (int nt = 0; nt < 8; nt++) {
        *(uint32_t*)&O0[nt * 8 + tig * 2] = packh(o[nt][0] * inv0, o[nt][1] * inv0);
        *(uint32_t*)&O1[nt * 8 + tig * 2] = packh(o[nt][2] * inv1, o[nt][3] * inv1);
    }
}

// ---------------- host orchestration ---------------------------------------
extern "C" void kernel_launch(void* const* d_in, const int* in_sizes, int n_in,
                              void* d_out, int out_size) {
    const float* hidden = (const float*)d_in[0];
    const float* rope   = (const float*)d_in[2];
    const float* ln0_g  = (const float*)d_in[3];
    const float* ln0_b  = (const float*)d_in[4];
    const float* ln1_g  = (const float*)d_in[5];
    const float* ln1_b  = (const float*)d_in[6];
    const float* w_qkv  = (const float*)d_in[7];
    const float* w_o    = (const float*)d_in[8];
    const float* w_fc0  = (const float*)d_in[9];
    const float* b_fc0  = (const float*)d_in[10];
    const float* w_fc1  = (const float*)d_in[11];
    const float* b_fc1  = (const float*)d_in[12];
    float* out = (float*)d_out;

    float  *p_h;
    __half *p_qkvh, *p_xlnh, *p_ylnh, *p_attnh, *p_fc0h;
    __half *p_wqkvc, *p_woc, *p_fc0c, *p_fc1c;
    cudaGetSymbolAddress((void**)&p_h,     g_h);
    cudaGetSymbolAddress((void**)&p_qkvh,  g_qkvh);
    cudaGetSymbolAddress((void**)&p_xlnh,  g_xlnh);
    cudaGetSymbolAddress((void**)&p_ylnh,  g_ylnh);
    cudaGetSymbolAddress((void**)&p_attnh, g_attnh);
    cudaGetSymbolAddress((void**)&p_fc0h,  g_fc0h);
    cudaGetSymbolAddress((void**)&p_wqkvc, g_wqkvc);
    cudaGetSymbolAddress((void**)&p_woc,   g_woc);
    cudaGetSymbolAddress((void**)&p_fc0c,  g_fc0c);
    cudaGetSymbolAddress((void**)&p_fc1c,  g_fc1c);

    cudaFuncSetAttribute(hgemm<1>, cudaFuncAttributeMaxDynamicSharedMemorySize, GEMM_SMEM_BYTES);
    cudaFuncSetAttribute(hgemm<2>, cudaFuncAttributeMaxDynamicSharedMemorySize, GEMM_SMEM_BYTES);
    cudaFuncSetAttribute(hgemm<3>, cudaFuncAttributeMaxDynamicSharedMemorySize, GEMM_SMEM_BYTES);
    cudaFuncSetAttribute(hgemm<4>, cudaFuncAttributeMaxDynamicSharedMemorySize, GEMM_SMEM_BYTES);

    // 0. weight converts fp32 -> half (layout preserved [K][N])
    cvt_h<<<(Dq * 3 * Dq) / 2048, 256>>>(w_qkv, p_wqkvc);
    cvt_h<<<(Dq * Dq) / 2048, 256>>>(w_o,   p_woc);
    cvt_h<<<(Dq * Mq) / 2048, 256>>>(w_fc0, p_fc0c);
    cvt_h<<<(Mq * Dq) / 2048, 256>>>(w_fc1, p_fc1c);

    // 1. LN0 -> half
    ln_kernel<<<Lq, 256>>>(hidden, ln0_g, ln0_b, p_xlnh);
    // 2. QKV = xln @ w_qkv, rope fused -> half
    hgemm<4><<<dim3(3 * Dq / 128, Lq / 128), 256, GEMM_SMEM_BYTES>>>(
        p_xlnh, p_wqkvc, nullptr, rope, p_qkvh, 3 * Dq, Dq);
    // 3. Attention -> half
    attn_kernel<<<dim3(8, Hq, 4), 256>>>();
    // 4. h = hidden + attn @ w_o -> fp32
    hgemm<2><<<dim3(Dq / 128, Lq / 128), 256, GEMM_SMEM_BYTES>>>(
        p_attnh, p_woc, nullptr, hidden, p_h, Dq, Dq);
    // 5. LN1 -> half
    ln_kernel<<<Lq, 256>>>(p_h, ln1_g, ln1_b, p_ylnh);
    // 6. fc0 + bias + gelu -> half
    hgemm<1><<<dim3(Mq / 128, Lq / 128), 256, GEMM_SMEM_BYTES>>>(
        p_ylnh, p_fc0c, b_fc0, nullptr, p_fc0h, Mq, Dq);
    // 7. out = h + fc0g @ w_fc1 + b_fc1 -> fp32
    hgemm<3><<<dim3(Dq / 128, Lq / 128), 256, GEMM_SMEM_BYTES>>>(
        p_fc0h, p_fc1c, b_fc1, p_h, out, Dq, Mq);
    (void)in_sizes; (void)n_in; (void)out_size;
}